// round 12
// baseline (speedup 1.0000x reference)
#include <cuda_runtime.h>
#include <cuda_bf16.h>
#include <mma.h>
#include <cstdint>

using namespace nvcuda;

// Problem constants
#define BATCH   4
#define T_SEQ   2048
#define D_MODEL 1024
#define NH      16
#define HD      64
#define M_ROWS  (BATCH * T_SEQ)   // 8192

// ---------------------------------------------------------------------------
// Scratch (device globals; referenced ONLY inside device code — see R5 note)
// ---------------------------------------------------------------------------
__device__ __nv_bfloat16 g_qh[(size_t)BATCH * NH * T_SEQ * HD];  // Q hi [bh][t][hd]
__device__ __nv_bfloat16 g_ql[(size_t)BATCH * NH * T_SEQ * HD];
__device__ __nv_bfloat16 g_kh[(size_t)BATCH * NH * T_SEQ * HD];
__device__ __nv_bfloat16 g_kl[(size_t)BATCH * NH * T_SEQ * HD];
__device__ __nv_bfloat16 g_vh[(size_t)BATCH * NH * T_SEQ * HD];
__device__ __nv_bfloat16 g_vl[(size_t)BATCH * NH * T_SEQ * HD];

__device__ __nv_bfloat16 g_Ah[(size_t)M_ROWS * D_MODEL];      // GEMM activation hi
__device__ __nv_bfloat16 g_Al[(size_t)M_ROWS * D_MODEL];      // GEMM activation lo
__device__ __nv_bfloat16 g_Wth[4][(size_t)D_MODEL * D_MODEL]; // W^T hi (K-major)
__device__ __nv_bfloat16 g_Wtl[4][(size_t)D_MODEL * D_MODEL]; // W^T lo

// ---------------------------------------------------------------------------
// sm_80-class PTX helpers (compute_103-safe)
// ---------------------------------------------------------------------------
__device__ __forceinline__ uint32_t smem_u32(const void* p) {
    uint32_t a;
    asm("{ .reg .u64 t; cvta.to.shared.u64 t, %1; cvt.u32.u64 %0, t; }" : "=r"(a) : "l"(p));
    return a;
}
#define CP_ASYNC16(saddr, gptr) \
    asm volatile("cp.async.cg.shared.global [%0], [%1], 16;" \
        :: "r"(saddr), "l"(gptr) : "memory")
#define CP_COMMIT() asm volatile("cp.async.commit_group;" ::: "memory")
#define CP_WAIT(n)  asm volatile("cp.async.wait_group %0;" :: "n"(n) : "memory")

#define LDSM_X4(r0, r1, r2, r3, addr) \
    asm volatile("ldmatrix.sync.aligned.m8n8.x4.shared.b16 {%0,%1,%2,%3}, [%4];" \
        : "=r"(r0), "=r"(r1), "=r"(r2), "=r"(r3) : "r"(addr))
#define LDSM_X4T(r0, r1, r2, r3, addr) \
    asm volatile("ldmatrix.sync.aligned.m8n8.x4.trans.shared.b16 {%0,%1,%2,%3}, [%4];" \
        : "=r"(r0), "=r"(r1), "=r"(r2), "=r"(r3) : "r"(addr))

// D += A*B, m16n8k16 row.col f32.bf16.bf16.f32
#define MMA16816(d, a, b0, b1) \
    asm volatile("mma.sync.aligned.m16n8k16.row.col.f32.bf16.bf16.f32 " \
        "{%0,%1,%2,%3}, {%4,%5,%6,%7}, {%8,%9}, {%0,%1,%2,%3};" \
        : "+f"((d)[0]), "+f"((d)[1]), "+f"((d)[2]), "+f"((d)[3]) \
        : "r"((a)[0]), "r"((a)[1]), "r"((a)[2]), "r"((a)[3]), "r"(b0), "r"(b1))

struct B3 { const float* b[3]; };
struct W4 { const float* W[4]; };

__device__ __forceinline__ void split2(float a, float b,
                                       __nv_bfloat162& h, __nv_bfloat162& l) {
    __nv_bfloat16 ha = __float2bfloat16(a), hb = __float2bfloat16(b);
    h.x = ha; h.y = hb;
    l.x = __float2bfloat16(a - __bfloat162float(ha));
    l.y = __float2bfloat16(b - __bfloat162float(hb));
}

// ---------------------------------------------------------------------------
// fp32 x -> bf16 hi/lo split (elementwise) into g_Ah/g_Al
// ---------------------------------------------------------------------------
__global__ __launch_bounds__(256)
void split_kernel(const float* __restrict__ xsrc)
{
    const int i = blockIdx.x * 256 + threadIdx.x;   // float4 index
    float4 v = ((const float4*)xsrc)[i];
    __nv_bfloat162 h0, l0, h1, l1;
    split2(v.x, v.y, h0, l0);
    split2(v.z, v.w, h1, l1);
    ((__nv_bfloat162*)g_Ah)[i * 2 + 0] = h0;
    ((__nv_bfloat162*)g_Ah)[i * 2 + 1] = h1;
    ((__nv_bfloat162*)g_Al)[i * 2 + 0] = l0;
    ((__nv_bfloat162*)g_Al)[i * 2 + 1] = l1;
}

// ---------------------------------------------------------------------------
// W [k,n] fp32 -> W^T [n,k] bf16 hi/lo, all 4 weights (z)
// ---------------------------------------------------------------------------
__global__ __launch_bounds__(256)
void wtrans_kernel(W4 w)
{
    __shared__ float tile[32][33];
    const int z = blockIdx.z;
    const float* __restrict__ W = w.W[z];
    const int n0 = blockIdx.x * 32, k0 = blockIdx.y * 32;
    const int tx = threadIdx.x & 31, ty = threadIdx.x >> 5;  // 32 x 8
#pragma unroll
    for (int i = 0; i < 4; i++)
        tile[ty + i * 8][tx] = W[(size_t)(k0 + ty + i * 8) * D_MODEL + n0 + tx];
    __syncthreads();
#pragma unroll
    for (int i = 0; i < 4; i++) {
        float v = tile[tx][ty + i * 8];
        __nv_bfloat16 h = __float2bfloat16(v);
        size_t idx = (size_t)(n0 + ty + i * 8) * D_MODEL + k0 + tx;
        g_Wth[z][idx] = h;
        g_Wtl[z][idx] = __float2bfloat16(v - __bfloat162float(h));
    }
}

// ---------------------------------------------------------------------------
// WMMA GEMM (math proven R6-R11): C[128x128] tile + bias.
// 2-stage cp.async ring (80KB) + launch_bounds(256,2) -> 2 blocks/SM.
// R12: term-major MMA order (longer dependency distance for the scheduler).
// ---------------------------------------------------------------------------
#define BK        32
#define NSTAGE    2
#define LDS_BF    40
#define MAT_B     (128 * LDS_BF * 2)          // 10240
#define STAGE_B   (4 * MAT_B)                 // 40960
#define GEMM_SMEM (NSTAGE * STAGE_B)          // 81920
#define NCHUNKS   (D_MODEL / BK)              // 32
#define EPI_LD    36

template <bool QKV>
__global__ __launch_bounds__(256, 2)
void wmma_gemm_kernel(B3 biases, float* __restrict__ Cout)
{
    extern __shared__ char smc[];
    const uint32_t smb = smem_u32(smc);
    const int tid = threadIdx.x;
    const int wid = tid >> 5;
    const int lid = tid & 31;

    const int z = QKV ? blockIdx.z : 3;
    const int rowBase = blockIdx.y * 128;
    const int colBase = blockIdx.x * 128;
    const float* __restrict__ bias = QKV ? biases.b[z] : biases.b[0];

    const __nv_bfloat16* __restrict__ src[4] = {
        g_Ah + (size_t)rowBase * D_MODEL,
        g_Al + (size_t)rowBase * D_MODEL,
        g_Wth[z] + (size_t)colBase * D_MODEL,
        g_Wtl[z] + (size_t)colBase * D_MODEL
    };

    const int wm = wid & 1;
    const int wn = wid >> 1;

    wmma::fragment<wmma::accumulator, 16, 16, 16, float> acc[4][2];
#pragma unroll
    for (int mf = 0; mf < 4; mf++)
#pragma unroll
        for (int nf = 0; nf < 2; nf++) wmma::fill_fragment(acc[mf][nf], 0.0f);

    auto load_stage = [&](int stage, int k0) {
        const uint32_t sb = smb + stage * STAGE_B;
#pragma unroll
        for (int mat = 0; mat < 4; ++mat) {
#pragma unroll
            for (int half = 0; half < 2; ++half) {
                const int e = tid + half * 256;
                const int row = e >> 2;
                const int c8 = e & 3;
                const __nv_bfloat16* g = src[mat] + (size_t)row * D_MODEL + k0 + c8 * 8;
                const uint32_t off = sb + mat * MAT_B
                                   + (uint32_t)(row * (LDS_BF * 2) + c8 * 16);
                CP_ASYNC16(off, g);
            }
        }
        CP_COMMIT();
    };

    load_stage(0, 0);

    for (int c = 0; c < NCHUNKS; ++c) {
        CP_WAIT(0);            // stage c landed
        __syncthreads();       // all warps past compute(c-1)
        if (c + 1 < NCHUNKS) load_stage((c + 1) & 1, (c + 1) * BK);

        const char* stg = smc + (c & 1) * STAGE_B;
        const __nv_bfloat16* Ah_s = (const __nv_bfloat16*)(stg + 0 * MAT_B);
        const __nv_bfloat16* Al_s = (const __nv_bfloat16*)(stg + 1 * MAT_B);
        const __nv_bfloat16* Bh_s = (const __nv_bfloat16*)(stg + 2 * MAT_B);
        const __nv_bfloat16* Bl_s = (const __nv_bfloat16*)(stg + 3 * MAT_B);

#pragma unroll
        for (int ks = 0; ks < 2; ++ks) {
            wmma::fragment<wmma::matrix_a, 16, 16, 16, __nv_bfloat16, wmma::row_major> ah[4], al[4];
#pragma unroll
            for (int mf = 0; mf < 4; ++mf) {
                const int ro = (wm * 64 + mf * 16) * LDS_BF + ks * 16;
                wmma::load_matrix_sync(ah[mf], Ah_s + ro, LDS_BF);
                wmma::load_matrix_sync(al[mf], Al_s + ro, LDS_BF);
            }
#pragma unroll
            for (int nf = 0; nf < 2; ++nf) {
                const int bo = (wn * 32 + nf * 16) * LDS_BF + ks * 16;
                wmma::fragment<wmma::matrix_b, 16, 16, 16, __nv_bfloat16, wmma::col_major> bh, bl;
                wmma::load_matrix_sync(bh, Bh_s + bo, LDS_BF);
                wmma::load_matrix_sync(bl, Bl_s + bo, LDS_BF);
                // term-major: all mf of one term before the next term
#pragma unroll
                for (int mf = 0; mf < 4; ++mf)
                    wmma::mma_sync(acc[mf][nf], ah[mf], bh, acc[mf][nf]);
#pragma unroll
                for (int mf = 0; mf < 4; ++mf)
                    wmma::mma_sync(acc[mf][nf], al[mf], bh, acc[mf][nf]);
#pragma unroll
                for (int mf = 0; mf < 4; ++mf)
                    wmma::mma_sync(acc[mf][nf], ah[mf], bl, acc[mf][nf]);
            }
        }
    }

    __syncthreads();
    float* wbuf = (float*)smc + wid * (64 * EPI_LD);
#pragma unroll
    for (int mf = 0; mf < 4; ++mf)
#pragma unroll
        for (int nf = 0; nf < 2; ++nf)
            wmma::store_matrix_sync(wbuf + (mf * 16) * EPI_LD + nf * 16,
                                    acc[mf][nf], EPI_LD, wmma::mem_row_major);
    __syncwarp();

#pragma unroll
    for (int i = 0; i < 16; ++i) {
        const int idx = lid + i * 32;
        const int row = idx >> 3;
        const int seg = idx & 7;
        float4 v = *(const float4*)&wbuf[row * EPI_LD + seg * 4];
        const int m = rowBase + wm * 64 + row;
        const int n = colBase + wn * 32 + seg * 4;
        v.x += __ldg(&bias[n + 0]);
        v.y += __ldg(&bias[n + 1]);
        v.z += __ldg(&bias[n + 2]);
        v.w += __ldg(&bias[n + 3]);
        if (QKV) {
            const int bh_ = (m >> 11) * NH + (n >> 6);
            const int t   = m & 2047;
            const int hd  = n & 63;
            const size_t base = ((size_t)bh_ * T_SEQ + t) * HD + hd;
            __nv_bfloat16 *dh, *dl;
            if (z == 0)      { dh = g_qh; dl = g_ql; }
            else if (z == 1) { dh = g_kh; dl = g_kl; }
            else             { dh = g_vh; dl = g_vl; }
            __nv_bfloat162 h0, l0, h1, l1;
            split2(v.x, v.y, h0, l0);
            split2(v.z, v.w, h1, l1);
            *(__nv_bfloat162*)(dh + base)     = h0;
            *(__nv_bfloat162*)(dh + base + 2) = h1;
            *(__nv_bfloat162*)(dl + base)     = l0;
            *(__nv_bfloat162*)(dl + base + 2) = l1;
        } else {
            *(float4*)&Cout[(size_t)m * D_MODEL + n] = v;
        }
    }
}

// ---------------------------------------------------------------------------
// Flash v5.2: FA2-style register-resident causal attention (raw mma.sync).
// Same math as R10/R11 (rel_err 1.66e-5). R12 change: volatile MMAs
// interleaved across the two accumulators of each n-tile pair so no two
// consecutive HMMAs share an accumulator (dep distance 1 -> 2). Per-acc
// term order unchanged => bit-identical results.
// Fragment maps: see R10 derivation (PTX ISA m16n8k16).
// ---------------------------------------------------------------------------
#define QTQ      128
#define KTK      64
#define FL_THR   256
#define FLD      144                           // bytes per 64-col bf16 row (padded)
#define MAT9     (KTK * FLD)                   // 9216 per matrix tile
#define STG_B    (4 * MAT9)                    // 36864: Kh Kl Vh Vl
#define FL_SMEM  (3 * STG_B)                   // 110592 (stage2 doubles as Q staging)

__global__ __launch_bounds__(FL_THR, 2)
void flash_fa2_kernel()
{
    extern __shared__ char smf[];
    const uint32_t smb = smem_u32(smf);

    const int tid  = threadIdx.x;
    const int w    = tid >> 5;
    const int lane = tid & 31;
    const int g    = lane >> 2;
    const int t    = lane & 3;
    const int bh   = blockIdx.y;
    const int qt   = gridDim.x - 1 - blockIdx.x;   // big tiles first
    const int ktmax = 2 * qt + 1;

    const size_t base = (size_t)bh * T_SEQ * HD;

    // per-lane ldmatrix address components (see R10 derivation)
    const uint32_t rK = (uint32_t)(((lane & 7) + ((lane & 16) ? 8 : 0)) * FLD
                                   + ((lane & 8) ? 16 : 0));
    const uint32_t rV = (uint32_t)(((lane & 7) + ((lane & 8) ? 8 : 0)) * FLD
                                   + ((lane & 16) ? 16 : 0));
    const uint32_t rQ = (uint32_t)((lane & 15) * FLD + ((lane & 16) ? 16 : 0));

    // ---- prologue: stage Q (hi/lo) into stage 2, prefetch kt=0 into stage 0
    {
        const __nv_bfloat16* qsrc[2] = { g_qh + base + (size_t)qt * QTQ * HD,
                                         g_ql + base + (size_t)qt * QTQ * HD };
#pragma unroll
        for (int m = 0; m < 2; ++m) {
            const uint32_t dst = smb + 2 * STG_B + m * (QTQ * FLD);
#pragma unroll
            for (int it = 0; it < 4; ++it) {
                const int e = tid + it * FL_THR;       // 0..1023
                const int r = e >> 3, s = e & 7;
                CP_ASYNC16(dst + (uint32_t)(r * FLD + s * 16),
                           qsrc[m] + (size_t)r * HD + s * 8);
            }
        }
        CP_COMMIT();   // G_Q
    }
    auto prefetch = [&](int kt_, int stage) {
        const uint32_t sb = smb + stage * STG_B;
        const size_t kb = base + (size_t)kt_ * KTK * HD;
        const __nv_bfloat16* gsrc[4] = { g_kh + kb, g_kl + kb, g_vh + kb, g_vl + kb };
#pragma unroll
        for (int mat = 0; mat < 4; ++mat) {
#pragma unroll
            for (int it = 0; it < 2; ++it) {
                const int e = tid + it * FL_THR;       // 0..511
                const int r = e >> 3, s = e & 7;
                CP_ASYNC16(sb + (uint32_t)(mat * MAT9 + r * FLD + s * 16),
                           gsrc[mat] + (size_t)r * HD + s * 8);
            }
        }
        CP_COMMIT();
    };
    prefetch(0, 0);                 // G_0
    CP_WAIT(1);                     // Q staged (G_0 may be in flight)
    __syncthreads();

    // ---- Q A-fragments to registers (once) ----
    uint32_t qhf[4][4], qlf[4][4];
    {
        const uint32_t q2 = smb + 2 * STG_B + (uint32_t)(w * 16) * FLD + rQ;
#pragma unroll
        for (int kg = 0; kg < 4; ++kg) {
            LDSM_X4(qhf[kg][0], qhf[kg][1], qhf[kg][2], qhf[kg][3], q2 + kg * 32);
            LDSM_X4(qlf[kg][0], qlf[kg][1], qlf[kg][2], qlf[kg][3], q2 + 18432u + kg * 32);
        }
    }
    if (1 <= ktmax) prefetch(1, 1); else CP_COMMIT();   // G_1

    float O[8][4];
#pragma unroll
    for (int j = 0; j < 8; ++j)
#pragma unroll
        for (int c = 0; c < 4; ++c) O[j][c] = 0.f;
    float lg = 0.f, lg8 = 0.f;
    const int rq0 = qt * QTQ + w * 16 + g;
    const int rq1 = rq0 + 8;

    for (int kt = 0; kt <= ktmax; ++kt) {
        CP_WAIT(1);        // stage kt ready (stage kt+1 may be in flight)
        __syncthreads();   // visibility + all warps done with stage kt-1
        if (kt + 2 <= ktmax) prefetch(kt + 2, (kt + 2) % 3); else CP_COMMIT();

        const uint32_t sb = smb + (kt % 3) * STG_B;

        // ---- S = Q K^T (3-term), regs; MMAs interleaved across S[2jj]/S[2jj+1]
        float S[8][4];
#pragma unroll
        for (int j = 0; j < 8; ++j)
#pragma unroll
            for (int c = 0; c < 4; ++c) S[j][c] = 0.f;

#pragma unroll
        for (int kg = 0; kg < 4; ++kg) {
#pragma unroll
            for (int jj = 0; jj < 4; ++jj) {   // key n-tiles j=2jj, 2jj+1
                const uint32_t ka = sb + (uint32_t)(jj * 2304 + kg * 32) + rK;
                uint32_t kh0, kh1, kh2, kh3, kl0, kl1, kl2, kl3;
                LDSM_X4(kh0, kh1, kh2, kh3, ka);
                LDSM_X4(kl0, kl1, kl2, kl3, ka + MAT9);
                MMA16816(S[2 * jj],     qhf[kg], kh0, kh1);
                MMA16816(S[2 * jj + 1], qhf[kg], kh2, kh3);
                MMA16816(S[2 * jj],     qlf[kg], kh0, kh1);
                MMA16816(S[2 * jj + 1], qlf[kg], kh2, kh3);
                MMA16816(S[2 * jj],     qhf[kg], kl0, kl1);
                MMA16816(S[2 * jj + 1], qhf[kg], kl2, kl3);
            }
        }

        // ---- mask + exp + l (regs) ----
#pragma unroll
        for (int j = 0; j < 8; ++j) {
            const int kb = kt * KTK + 8 * j + 2 * t;
            S[j][0] = (kb     <= rq0) ? __expf(S[j][0] * 0.125f) : 0.f;
            S[j][1] = (kb + 1 <= rq0) ? __expf(S[j][1] * 0.125f) : 0.f;
            S[j][2] = (kb     <= rq1) ? __expf(S[j][2] * 0.125f) : 0.f;
            S[j][3] = (kb + 1 <= rq1) ? __expf(S[j][3] * 0.125f) : 0.f;
            lg  += S[j][0] + S[j][1];
            lg8 += S[j][2] + S[j][3];
        }

        // ---- per key-group: pack P hi/lo (transient) then PV MMAs,
        //      interleaved across O[2jj]/O[2jj+1] ----
#pragma unroll
        for (int kg = 0; kg < 4; ++kg) {
            uint32_t ph[4], pl[4];
            {
                __nv_bfloat162 h2, l2;
                split2(S[2 * kg][0], S[2 * kg][1], h2, l2);
                ph[0] = *(uint32_t*)&h2; pl[0] = *(uint32_t*)&l2;
                split2(S[2 * kg][2], S[2 * kg][3], h2, l2);
                ph[1] = *(uint32_t*)&h2; pl[1] = *(uint32_t*)&l2;
                split2(S[2 * kg + 1][0], S[2 * kg + 1][1], h2, l2);
                ph[2] = *(uint32_t*)&h2; pl[2] = *(uint32_t*)&l2;
                split2(S[2 * kg + 1][2], S[2 * kg + 1][3], h2, l2);
                ph[3] = *(uint32_t*)&h2; pl[3] = *(uint32_t*)&l2;
            }
#pragma unroll
            for (int jj = 0; jj < 4; ++jj) { // hd n-tiles j=2jj, 2jj+1
                const uint32_t va = sb + (uint32_t)(2 * MAT9 + kg * 2304 + jj * 32) + rV;
                uint32_t vh0, vh1, vh2, vh3, vl0, vl1, vl2, vl3;
                LDSM_X4T(vh0, vh1, vh2, vh3, va);
                LDSM_X4T(vl0, vl1, vl2, vl3, va + MAT9);
                MMA16816(O[2 * jj],     ph, vh0, vh1);
                MMA16816(O[2 * jj + 1], ph, vh2, vh3);
                MMA16816(O[2 * jj],     pl, vh0, vh1);
                MMA16816(O[2 * jj + 1], pl, vh2, vh3);
                MMA16816(O[2 * jj],     ph, vl0, vl1);
                MMA16816(O[2 * jj + 1], ph, vl2, vl3);
            }
        }
    }

    // ---- epilogue: row sums across quad, normalize, split, write ----
    lg  += __shfl_xor_sync(0xffffffffu, lg, 1);
    lg  += __shfl_xor_sync(0xffffffffu, lg, 2);
    lg8 += __shfl_xor_sync(0xffffffffu, lg8, 1);
    lg8 += __shfl_xor_sync(0xffffffffu, lg8, 2);
    const float li0 = 1.0f / lg;
    const float li8 = 1.0f / lg8;

    const int b = bh >> 4, h = bh & 15;
    const int rq0g = qt * QTQ + w * 16 + g;
    const size_t ob0 = ((size_t)(b * T_SEQ + rq0g)) * D_MODEL + h * HD;
    const size_t ob1 = ((size_t)(b * T_SEQ + rq0g + 8)) * D_MODEL + h * HD;
#pragma unroll
    for (int j = 0; j < 8; ++j) {
        const int col = 8 * j + 2 * t;
        __nv_bfloat162 h2, l2;
        split2(O[j][0] * li0, O[j][1] * li0, h2, l2);
        *(__nv_bfloat162*)&g_Ah[ob0 + col] = h2;
        *(__nv_bfloat162*)&g_Al[ob0 + col] = l2;
        split2(O[j][2] * li8, O[j][3] * li8, h2, l2);
        *(__nv_bfloat162*)&g_Ah[ob1 + col] = h2;
        *(__nv_bfloat162*)&g_Al[ob1 + col] = l2;
    }
}

// ---------------------------------------------------------------------------
extern "C" void kernel_launch(void* const* d_in, const int* in_sizes, int n_in,
                              void* d_out, int out_size)
{
    (void)in_sizes; (void)n_in; (void)out_size;
    const float* x  = (const float*)d_in[0];
    const float* Wq = (const float*)d_in[1];
    const float* bq = (const float*)d_in[2];
    const float* Wk = (const float*)d_in[3];
    const float* bk = (const float*)d_in[4];
    const float* Wv = (const float*)d_in[5];
    const float* bv = (const float*)d_in[6];
    const float* Wo = (const float*)d_in[7];
    const float* bo = (const float*)d_in[8];
    float* out = (float*)d_out;

    cudaFuncSetAttribute(wmma_gemm_kernel<true>,
                         cudaFuncAttributeMaxDynamicSharedMemorySize, GEMM_SMEM);
    cudaFuncSetAttribute(wmma_gemm_kernel<false>,
                         cudaFuncAttributeMaxDynamicSharedMemorySize, GEMM_SMEM);
    cudaFuncSetAttribute(flash_fa2_kernel,
                         cudaFuncAttributeMaxDynamicSharedMemorySize, FL_SMEM);

    // 0) split x -> g_Ah/g_Al; transpose+split weights
    split_kernel<<<M_ROWS * D_MODEL / 1024, 256>>>(x);
    W4 w4; w4.W[0] = Wq; w4.W[1] = Wk; w4.W[2] = Wv; w4.W[3] = Wo;
    wtrans_kernel<<<dim3(32, 32, 4), 256>>>(w4);

    // 1) QKV projections -> bf16 hi/lo Q/K/V [bh][t][hd]
    B3 bqkv; bqkv.b[0] = bq; bqkv.b[1] = bk; bqkv.b[2] = bv;
    wmma_gemm_kernel<true><<<dim3(D_MODEL / 128, M_ROWS / 128, 3), 256, GEMM_SMEM>>>(bqkv, nullptr);

    // 2) causal flash v5.2 (interleaved MMA chains) -> g_Ah/g_Al
    flash_fa2_kernel<<<dim3(T_SEQ / QTQ, BATCH * NH), FL_THR, FL_SMEM>>>();

    // 3) O projection -> d_out
    B3 bout; bout.b[0] = bo; bout.b[1] = bo; bout.b[2] = bo;
    wmma_gemm_kernel<false><<<dim3(D_MODEL / 128, M_ROWS / 128, 1), 256, GEMM_SMEM>>>(bout, out);
}

// round 14
// speedup vs baseline: 1.1050x; 1.1050x over previous
#include <cuda_runtime.h>
#include <cuda_bf16.h>
#include <cstdint>

// Problem constants
#define BATCH   4
#define T_SEQ   2048
#define D_MODEL 1024
#define NH      16
#define HD      64
#define M_ROWS  (BATCH * T_SEQ)   // 8192

// ---------------------------------------------------------------------------
// Scratch (device globals; referenced ONLY inside device code — see R5 note)
// ---------------------------------------------------------------------------
__device__ __nv_bfloat16 g_qh[(size_t)BATCH * NH * T_SEQ * HD];  // Q hi [bh][t][hd]
__device__ __nv_bfloat16 g_ql[(size_t)BATCH * NH * T_SEQ * HD];
__device__ __nv_bfloat16 g_kh[(size_t)BATCH * NH * T_SEQ * HD];
__device__ __nv_bfloat16 g_kl[(size_t)BATCH * NH * T_SEQ * HD];
__device__ __nv_bfloat16 g_vh[(size_t)BATCH * NH * T_SEQ * HD];
__device__ __nv_bfloat16 g_vl[(size_t)BATCH * NH * T_SEQ * HD];

__device__ __nv_bfloat16 g_Ah[(size_t)M_ROWS * D_MODEL];      // GEMM activation hi
__device__ __nv_bfloat16 g_Al[(size_t)M_ROWS * D_MODEL];      // GEMM activation lo
__device__ __nv_bfloat16 g_Wth[4][(size_t)D_MODEL * D_MODEL]; // W^T hi (K-major)
__device__ __nv_bfloat16 g_Wtl[4][(size_t)D_MODEL * D_MODEL]; // W^T lo

// ---------------------------------------------------------------------------
// sm_80-class PTX helpers (compute_103-safe)
// ---------------------------------------------------------------------------
__device__ __forceinline__ uint32_t smem_u32(const void* p) {
    uint32_t a;
    asm("{ .reg .u64 t; cvta.to.shared.u64 t, %1; cvt.u32.u64 %0, t; }" : "=r"(a) : "l"(p));
    return a;
}
#define CP_ASYNC16(saddr, gptr) \
    asm volatile("cp.async.cg.shared.global [%0], [%1], 16;" \
        :: "r"(saddr), "l"(gptr) : "memory")
#define CP_COMMIT() asm volatile("cp.async.commit_group;" ::: "memory")
#define CP_WAIT(n)  asm volatile("cp.async.wait_group %0;" :: "n"(n) : "memory")

#define LDSM_X4(r0, r1, r2, r3, addr) \
    asm volatile("ldmatrix.sync.aligned.m8n8.x4.shared.b16 {%0,%1,%2,%3}, [%4];" \
        : "=r"(r0), "=r"(r1), "=r"(r2), "=r"(r3) : "r"(addr))
#define LDSM_X4T(r0, r1, r2, r3, addr) \
    asm volatile("ldmatrix.sync.aligned.m8n8.x4.trans.shared.b16 {%0,%1,%2,%3}, [%4];" \
        : "=r"(r0), "=r"(r1), "=r"(r2), "=r"(r3) : "r"(addr))

// D += A*B, m16n8k16 row.col f32.bf16.bf16.f32
#define MMA16816(d, a, b0, b1) \
    asm volatile("mma.sync.aligned.m16n8k16.row.col.f32.bf16.bf16.f32 " \
        "{%0,%1,%2,%3}, {%4,%5,%6,%7}, {%8,%9}, {%0,%1,%2,%3};" \
        : "+f"((d)[0]), "+f"((d)[1]), "+f"((d)[2]), "+f"((d)[3]) \
        : "r"((a)[0]), "r"((a)[1]), "r"((a)[2]), "r"((a)[3]), "r"(b0), "r"(b1))

struct B3 { const float* b[3]; };
struct W4 { const float* W[4]; };

__device__ __forceinline__ void split2(float a, float b,
                                       __nv_bfloat162& h, __nv_bfloat162& l) {
    __nv_bfloat16 ha = __float2bfloat16(a), hb = __float2bfloat16(b);
    h.x = ha; h.y = hb;
    l.x = __float2bfloat16(a - __bfloat162float(ha));
    l.y = __float2bfloat16(b - __bfloat162float(hb));
}

// ---------------------------------------------------------------------------
// fp32 x -> bf16 hi/lo split (elementwise) into g_Ah/g_Al
// ---------------------------------------------------------------------------
__global__ __launch_bounds__(256)
void split_kernel(const float* __restrict__ xsrc)
{
    const int i = blockIdx.x * 256 + threadIdx.x;   // float4 index
    float4 v = ((const float4*)xsrc)[i];
    __nv_bfloat162 h0, l0, h1, l1;
    split2(v.x, v.y, h0, l0);
    split2(v.z, v.w, h1, l1);
    ((__nv_bfloat162*)g_Ah)[i * 2 + 0] = h0;
    ((__nv_bfloat162*)g_Ah)[i * 2 + 1] = h1;
    ((__nv_bfloat162*)g_Al)[i * 2 + 0] = l0;
    ((__nv_bfloat162*)g_Al)[i * 2 + 1] = l1;
}

// ---------------------------------------------------------------------------
// W [k,n] fp32 -> W^T [n,k] bf16 hi/lo, all 4 weights (z)
// ---------------------------------------------------------------------------
__global__ __launch_bounds__(256)
void wtrans_kernel(W4 w)
{
    __shared__ float tile[32][33];
    const int z = blockIdx.z;
    const float* __restrict__ W = w.W[z];
    const int n0 = blockIdx.x * 32, k0 = blockIdx.y * 32;
    const int tx = threadIdx.x & 31, ty = threadIdx.x >> 5;  // 32 x 8
#pragma unroll
    for (int i = 0; i < 4; i++)
        tile[ty + i * 8][tx] = W[(size_t)(k0 + ty + i * 8) * D_MODEL + n0 + tx];
    __syncthreads();
#pragma unroll
    for (int i = 0; i < 4; i++) {
        float v = tile[tx][ty + i * 8];
        __nv_bfloat16 h = __float2bfloat16(v);
        size_t idx = (size_t)(n0 + ty + i * 8) * D_MODEL + k0 + tx;
        g_Wth[z][idx] = h;
        g_Wtl[z][idx] = __float2bfloat16(v - __bfloat162float(h));
    }
}

// ---------------------------------------------------------------------------
// RAW-MMA GEMM (R13/R14): C[128x128] tile of A(8192x1024) @ W(1024x1024) + bias.
// Fragment recipes identical to the R10-verified flash maps:
//   A-frag addr = (lane&15)*LD + ((lane&16)?16:0)                 (flash Q)
//   B-frag addr = ((lane&7)+((lane&16)?8:0))*LD + ((lane&8)?16:0) (flash K)
//   C layout: c0,c1 -> (g, 2t,2t+1), c2,c3 -> (g+8)               (flash O)
// 8 warps = 2(M) x 4(N); warp tile 64x32; BK=32; 2-stage cp.async; 80B rows
// (conflict-free LDSM). Direct-register epilogue (no smem staging/barrier).
// 3-term bf16 split, term-major interleaved MMAs.
// ---------------------------------------------------------------------------
#define BK        32
#define GFLD      80                           // bytes per 32-bf16 row (padded)
#define GMAT      (128 * GFLD)                 // 10240
#define GSTG      (4 * GMAT)                   // 40960: Ah Al Bh Bl
#define GEMM_SMEM (2 * GSTG)                   // 81920 -> 2 blocks/SM
#define NCHUNKS   (D_MODEL / BK)               // 32

template <bool QKV>
__global__ __launch_bounds__(256, 2)
void mma_gemm_kernel(B3 biases, float* __restrict__ Cout)
{
    extern __shared__ char smc[];
    const uint32_t smb = smem_u32(smc);
    const int tid  = threadIdx.x;
    const int wid  = tid >> 5;
    const int lane = tid & 31;
    const int g    = lane >> 2;
    const int t    = lane & 3;

    const int z = QKV ? blockIdx.z : 3;
    const int rowBase = blockIdx.y * 128;
    const int colBase = blockIdx.x * 128;
    const float* __restrict__ bias = QKV ? biases.b[z] : biases.b[0];

    const __nv_bfloat16* __restrict__ src[4] = {
        g_Ah + (size_t)rowBase * D_MODEL,
        g_Al + (size_t)rowBase * D_MODEL,
        g_Wth[z] + (size_t)colBase * D_MODEL,
        g_Wtl[z] + (size_t)colBase * D_MODEL
    };

    const int wm = wid & 1;          // M half (64 rows)
    const int wn = wid >> 1;         // N quarter (32 cols)

    const uint32_t rA = (uint32_t)((lane & 15) * GFLD + ((lane & 16) ? 16 : 0));
    const uint32_t rB = (uint32_t)(((lane & 7) + ((lane & 16) ? 8 : 0)) * GFLD
                                   + ((lane & 8) ? 16 : 0));

    float acc[4][4][4];              // [mf][n8][4]
#pragma unroll
    for (int mf = 0; mf < 4; ++mf)
#pragma unroll
        for (int n8 = 0; n8 < 4; ++n8)
#pragma unroll
            for (int c = 0; c < 4; ++c) acc[mf][n8][c] = 0.f;

    auto load_stage = [&](int stage, int k0) {
        const uint32_t sb = smb + stage * GSTG;
#pragma unroll
        for (int mat = 0; mat < 4; ++mat) {
#pragma unroll
            for (int half = 0; half < 2; ++half) {
                const int e = tid + half * 256;      // 0..511
                const int row = e >> 2;              // 0..127
                const int c4 = e & 3;                // 16B chunk
                CP_ASYNC16(sb + (uint32_t)(mat * GMAT + row * GFLD + c4 * 16),
                           src[mat] + (size_t)row * D_MODEL + k0 + c4 * 8);
            }
        }
        CP_COMMIT();
    };

    load_stage(0, 0);

    for (int c = 0; c < NCHUNKS; ++c) {
        CP_WAIT(0);            // stage c landed
        __syncthreads();       // all warps past compute(c-1)
        if (c + 1 < NCHUNKS) load_stage((c + 1) & 1, (c + 1) * BK);

        const uint32_t sb = smb + (c & 1) * GSTG;
        const uint32_t aRow = sb + (uint32_t)(wm * 64) * GFLD + rA;
        const uint32_t bRow = sb + 2 * GMAT + (uint32_t)(wn * 32) * GFLD + rB;

#pragma unroll
        for (int ks = 0; ks < 2; ++ks) {
            const uint32_t ko = (uint32_t)(ks * 32);
            // ---- term 1: Ah x Bh ----
            uint32_t ah[4][4], bh[2][4];
#pragma unroll
            for (int mf = 0; mf < 4; ++mf)
                LDSM_X4(ah[mf][0], ah[mf][1], ah[mf][2], ah[mf][3],
                        aRow + (uint32_t)(mf * 16) * GFLD + ko);
#pragma unroll
            for (int j2 = 0; j2 < 2; ++j2)
                LDSM_X4(bh[j2][0], bh[j2][1], bh[j2][2], bh[j2][3],
                        bRow + (uint32_t)(j2 * 16) * GFLD + ko);
#pragma unroll
            for (int mf = 0; mf < 4; ++mf)
#pragma unroll
                for (int j2 = 0; j2 < 2; ++j2) {
                    MMA16816(acc[mf][2 * j2],     ah[mf], bh[j2][0], bh[j2][1]);
                    MMA16816(acc[mf][2 * j2 + 1], ah[mf], bh[j2][2], bh[j2][3]);
                }
            // ---- term 2: Al x Bh ----
            uint32_t al[4][4];
#pragma unroll
            for (int mf = 0; mf < 4; ++mf)
                LDSM_X4(al[mf][0], al[mf][1], al[mf][2], al[mf][3],
                        aRow + GMAT + (uint32_t)(mf * 16) * GFLD + ko);
#pragma unroll
            for (int mf = 0; mf < 4; ++mf)
#pragma unroll
                for (int j2 = 0; j2 < 2; ++j2) {
                    MMA16816(acc[mf][2 * j2],     al[mf], bh[j2][0], bh[j2][1]);
                    MMA16816(acc[mf][2 * j2 + 1], al[mf], bh[j2][2], bh[j2][3]);
                }
            // ---- term 3: Ah x Bl ----
            uint32_t bl[2][4];
#pragma unroll
            for (int j2 = 0; j2 < 2; ++j2)
                LDSM_X4(bl[j2][0], bl[j2][1], bl[j2][2], bl[j2][3],
                        bRow + GMAT + (uint32_t)(j2 * 16) * GFLD + ko);
#pragma unroll
            for (int mf = 0; mf < 4; ++mf)
#pragma unroll
                for (int j2 = 0; j2 < 2; ++j2) {
                    MMA16816(acc[mf][2 * j2],     ah[mf], bl[j2][0], bl[j2][1]);
                    MMA16816(acc[mf][2 * j2 + 1], ah[mf], bl[j2][2], bl[j2][3]);
                }
        }
    }

    // ---- direct-register epilogue (flash-O layout), no smem staging ----
#pragma unroll
    for (int mf = 0; mf < 4; ++mf) {
        const int row0 = rowBase + wm * 64 + mf * 16 + g;
#pragma unroll
        for (int n8 = 0; n8 < 4; ++n8) {
            const int col = colBase + wn * 32 + n8 * 8 + 2 * t;
            const float bx = __ldg(&bias[col]);
            const float by = __ldg(&bias[col + 1]);
            float2 v0 = { acc[mf][n8][0] + bx, acc[mf][n8][1] + by };
            float2 v1 = { acc[mf][n8][2] + bx, acc[mf][n8][3] + by };
            if (QKV) {
                __nv_bfloat16 *dh, *dl;
                if (z == 0)      { dh = g_qh; dl = g_ql; }
                else if (z == 1) { dh = g_kh; dl = g_kl; }
                else             { dh = g_vh; dl = g_vl; }
                const int hd = col & 63;
                const int hh = col >> 6;
#pragma unroll
                for (int r = 0; r < 2; ++r) {
                    const int row = row0 + r * 8;
                    const int bh_ = (row >> 11) * NH + hh;
                    const int tt  = row & 2047;
                    const size_t o = ((size_t)bh_ * T_SEQ + tt) * HD + hd;
                    __nv_bfloat162 h2, l2;
                    split2(r ? v1.x : v0.x, r ? v1.y : v0.y, h2, l2);
                    *(__nv_bfloat162*)(dh + o) = h2;
                    *(__nv_bfloat162*)(dl + o) = l2;
                }
            } else {
                *(float2*)&Cout[(size_t)row0 * D_MODEL + col] = v0;
                *(float2*)&Cout[(size_t)(row0 + 8) * D_MODEL + col] = v1;
            }
        }
    }
}

// ---------------------------------------------------------------------------
// Flash v5.2 (byte-identical to R12; proven rel_err 1.66e-5)
// ---------------------------------------------------------------------------
#define QTQ      128
#define KTK      64
#define FL_THR   256
#define FLD      144
#define MAT9     (KTK * FLD)                   // 9216
#define STG_B    (4 * MAT9)                    // 36864
#define FL_SMEM  (3 * STG_B)                   // 110592

__global__ __launch_bounds__(FL_THR, 2)
void flash_fa2_kernel()
{
    extern __shared__ char smf[];
    const uint32_t smb = smem_u32(smf);

    const int tid  = threadIdx.x;
    const int w    = tid >> 5;
    const int lane = tid & 31;
    const int g    = lane >> 2;
    const int t    = lane & 3;
    const int bh   = blockIdx.y;
    const int qt   = gridDim.x - 1 - blockIdx.x;
    const int ktmax = 2 * qt + 1;

    const size_t base = (size_t)bh * T_SEQ * HD;

    const uint32_t rK = (uint32_t)(((lane & 7) + ((lane & 16) ? 8 : 0)) * FLD
                                   + ((lane & 8) ? 16 : 0));
    const uint32_t rV = (uint32_t)(((lane & 7) + ((lane & 8) ? 8 : 0)) * FLD
                                   + ((lane & 16) ? 16 : 0));
    const uint32_t rQ = (uint32_t)((lane & 15) * FLD + ((lane & 16) ? 16 : 0));

    {
        const __nv_bfloat16* qsrc[2] = { g_qh + base + (size_t)qt * QTQ * HD,
                                         g_ql + base + (size_t)qt * QTQ * HD };
#pragma unroll
        for (int m = 0; m < 2; ++m) {
            const uint32_t dst = smb + 2 * STG_B + m * (QTQ * FLD);
#pragma unroll
            for (int it = 0; it < 4; ++it) {
                const int e = tid + it * FL_THR;
                const int r = e >> 3, s = e & 7;
                CP_ASYNC16(dst + (uint32_t)(r * FLD + s * 16),
                           qsrc[m] + (size_t)r * HD + s * 8);
            }
        }
        CP_COMMIT();
    }
    auto prefetch = [&](int kt_, int stage) {
        const uint32_t sb = smb + stage * STG_B;
        const size_t kb = base + (size_t)kt_ * KTK * HD;
        const __nv_bfloat16* gsrc[4] = { g_kh + kb, g_kl + kb, g_vh + kb, g_vl + kb };
#pragma unroll
        for (int mat = 0; mat < 4; ++mat) {
#pragma unroll
            for (int it = 0; it < 2; ++it) {
                const int e = tid + it * FL_THR;
                const int r = e >> 3, s = e & 7;
                CP_ASYNC16(sb + (uint32_t)(mat * MAT9 + r * FLD + s * 16),
                           gsrc[mat] + (size_t)r * HD + s * 8);
            }
        }
        CP_COMMIT();
    };
    prefetch(0, 0);
    CP_WAIT(1);
    __syncthreads();

    uint32_t qhf[4][4], qlf[4][4];
    {
        const uint32_t q2 = smb + 2 * STG_B + (uint32_t)(w * 16) * FLD + rQ;
#pragma unroll
        for (int kg = 0; kg < 4; ++kg) {
            LDSM_X4(qhf[kg][0], qhf[kg][1], qhf[kg][2], qhf[kg][3], q2 + kg * 32);
            LDSM_X4(qlf[kg][0], qlf[kg][1], qlf[kg][2], qlf[kg][3], q2 + 18432u + kg * 32);
        }
    }
    if (1 <= ktmax) prefetch(1, 1); else CP_COMMIT();

    float O[8][4];
#pragma unroll
    for (int j = 0; j < 8; ++j)
#pragma unroll
        for (int c = 0; c < 4; ++c) O[j][c] = 0.f;
    float lg = 0.f, lg8 = 0.f;
    const int rq0 = qt * QTQ + w * 16 + g;
    const int rq1 = rq0 + 8;

    for (int kt = 0; kt <= ktmax; ++kt) {
        CP_WAIT(1);
        __syncthreads();
        if (kt + 2 <= ktmax) prefetch(kt + 2, (kt + 2) % 3); else CP_COMMIT();

        const uint32_t sb = smb + (kt % 3) * STG_B;

        float S[8][4];
#pragma unroll
        for (int j = 0; j < 8; ++j)
#pragma unroll
            for (int c = 0; c < 4; ++c) S[j][c] = 0.f;

#pragma unroll
        for (int kg = 0; kg < 4; ++kg) {
#pragma unroll
            for (int jj = 0; jj < 4; ++jj) {
                const uint32_t ka = sb + (uint32_t)(jj * 2304 + kg * 32) + rK;
                uint32_t kh0, kh1, kh2, kh3, kl0, kl1, kl2, kl3;
                LDSM_X4(kh0, kh1, kh2, kh3, ka);
                LDSM_X4(kl0, kl1, kl2, kl3, ka + MAT9);
                MMA16816(S[2 * jj],     qhf[kg], kh0, kh1);
                MMA16816(S[2 * jj + 1], qhf[kg], kh2, kh3);
                MMA16816(S[2 * jj],     qlf[kg], kh0, kh1);
                MMA16816(S[2 * jj + 1], qlf[kg], kh2, kh3);
                MMA16816(S[2 * jj],     qhf[kg], kl0, kl1);
                MMA16816(S[2 * jj + 1], qhf[kg], kl2, kl3);
            }
        }

#pragma unroll
        for (int j = 0; j < 8; ++j) {
            const int kb = kt * KTK + 8 * j + 2 * t;
            S[j][0] = (kb     <= rq0) ? __expf(S[j][0] * 0.125f) : 0.f;
            S[j][1] = (kb + 1 <= rq0) ? __expf(S[j][1] * 0.125f) : 0.f;
            S[j][2] = (kb     <= rq1) ? __expf(S[j][2] * 0.125f) : 0.f;
            S[j][3] = (kb + 1 <= rq1) ? __expf(S[j][3] * 0.125f) : 0.f;
            lg  += S[j][0] + S[j][1];
            lg8 += S[j][2] + S[j][3];
        }

#pragma unroll
        for (int kg = 0; kg < 4; ++kg) {
            uint32_t ph[4], pl[4];
            {
                __nv_bfloat162 h2, l2;
                split2(S[2 * kg][0], S[2 * kg][1], h2, l2);
                ph[0] = *(uint32_t*)&h2; pl[0] = *(uint32_t*)&l2;
                split2(S[2 * kg][2], S[2 * kg][3], h2, l2);
                ph[1] = *(uint32_t*)&h2; pl[1] = *(uint32_t*)&l2;
                split2(S[2 * kg + 1][0], S[2 * kg + 1][1], h2, l2);
                ph[2] = *(uint32_t*)&h2; pl[2] = *(uint32_t*)&l2;
                split2(S[2 * kg + 1][2], S[2 * kg + 1][3], h2, l2);
                ph[3] = *(uint32_t*)&h2; pl[3] = *(uint32_t*)&l2;
            }
#pragma unroll
            for (int jj = 0; jj < 4; ++jj) {
                const uint32_t va = sb + (uint32_t)(2 * MAT9 + kg * 2304 + jj * 32) + rV;
                uint32_t vh0, vh1, vh2, vh3, vl0, vl1, vl2, vl3;
                LDSM_X4T(vh0, vh1, vh2, vh3, va);
                LDSM_X4T(vl0, vl1, vl2, vl3, va + MAT9);
                MMA16816(O[2 * jj],     ph, vh0, vh1);
                MMA16816(O[2 * jj + 1], ph, vh2, vh3);
                MMA16816(O[2 * jj],     pl, vh0, vh1);
                MMA16816(O[2 * jj + 1], pl, vh2, vh3);
                MMA16816(O[2 * jj],     ph, vl0, vl1);
                MMA16816(O[2 * jj + 1], ph, vl2, vl3);
            }
        }
    }

    lg  += __shfl_xor_sync(0xffffffffu, lg, 1);
    lg  += __shfl_xor_sync(0xffffffffu, lg, 2);
    lg8 += __shfl_xor_sync(0xffffffffu, lg8, 1);
    lg8 += __shfl_xor_sync(0xffffffffu, lg8, 2);
    const float li0 = 1.0f / lg;
    const float li8 = 1.0f / lg8;

    const int b = bh >> 4, h = bh & 15;
    const int rq0g = qt * QTQ + w * 16 + g;
    const size_t ob0 = ((size_t)(b * T_SEQ + rq0g)) * D_MODEL + h * HD;
    const size_t ob1 = ((size_t)(b * T_SEQ + rq0g + 8)) * D_MODEL + h * HD;
#pragma unroll
    for (int j = 0; j < 8; ++j) {
        const int col = 8 * j + 2 * t;
        __nv_bfloat162 h2, l2;
        split2(O[j][0] * li0, O[j][1] * li0, h2, l2);
        *(__nv_bfloat162*)&g_Ah[ob0 + col] = h2;
        *(__nv_bfloat162*)&g_Al[ob0 + col] = l2;
        split2(O[j][2] * li8, O[j][3] * li8, h2, l2);
        *(__nv_bfloat162*)&g_Ah[ob1 + col] = h2;
        *(__nv_bfloat162*)&g_Al[ob1 + col] = l2;
    }
}

// ---------------------------------------------------------------------------
extern "C" void kernel_launch(void* const* d_in, const int* in_sizes, int n_in,
                              void* d_out, int out_size)
{
    (void)in_sizes; (void)n_in; (void)out_size;
    const float* x  = (const float*)d_in[0];
    const float* Wq = (const float*)d_in[1];
    const float* bq = (const float*)d_in[2];
    const float* Wk = (const float*)d_in[3];
    const float* bk = (const float*)d_in[4];
    const float* Wv = (const float*)d_in[5];
    const float* bv = (const float*)d_in[6];
    const float* Wo = (const float*)d_in[7];
    const float* bo = (const float*)d_in[8];
    float* out = (float*)d_out;

    cudaFuncSetAttribute(mma_gemm_kernel<true>,
                         cudaFuncAttributeMaxDynamicSharedMemorySize, GEMM_SMEM);
    cudaFuncSetAttribute(mma_gemm_kernel<false>,
                         cudaFuncAttributeMaxDynamicSharedMemorySize, GEMM_SMEM);
    cudaFuncSetAttribute(flash_fa2_kernel,
                         cudaFuncAttributeMaxDynamicSharedMemorySize, FL_SMEM);

    // 0) split x -> g_Ah/g_Al; transpose+split weights
    split_kernel<<<M_ROWS * D_MODEL / 1024, 256>>>(x);
    W4 w4; w4.W[0] = Wq; w4.W[1] = Wk; w4.W[2] = Wv; w4.W[3] = Wo;
    wtrans_kernel<<<dim3(32, 32, 4), 256>>>(w4);

    // 1) QKV projections (raw-mma GEMM) -> bf16 hi/lo Q/K/V [bh][t][hd]
    B3 bqkv; bqkv.b[0] = bq; bqkv.b[1] = bk; bqkv.b[2] = bv;
    mma_gemm_kernel<true><<<dim3(D_MODEL / 128, M_ROWS / 128, 3), 256, GEMM_SMEM>>>(bqkv, nullptr);

    // 2) causal flash v5.2 -> g_Ah/g_Al
    flash_fa2_kernel<<<dim3(T_SEQ / QTQ, BATCH * NH), FL_THR, FL_SMEM>>>();

    // 3) O projection (raw-mma GEMM) -> d_out
    B3 bout; bout.b[0] = bo; bout.b[1] = bo; bout.b[2] = bo;
    mma_gemm_kernel<false><<<dim3(D_MODEL / 128, M_ROWS / 128, 1), 256, GEMM_SMEM>>>(bout, out);
}

// round 15
// speedup vs baseline: 1.1186x; 1.0123x over previous
#include <cuda_runtime.h>
#include <cuda_bf16.h>
#include <cstdint>

// Problem constants
#define BATCH   4
#define T_SEQ   2048
#define D_MODEL 1024
#define NH      16
#define HD      64
#define M_ROWS  (BATCH * T_SEQ)   // 8192

// ---------------------------------------------------------------------------
// Scratch (device globals; referenced ONLY inside device code — see R5 note)
// ---------------------------------------------------------------------------
__device__ __nv_bfloat16 g_qh[(size_t)BATCH * NH * T_SEQ * HD];  // Q hi [bh][t][hd]
__device__ __nv_bfloat16 g_ql[(size_t)BATCH * NH * T_SEQ * HD];
__device__ __nv_bfloat16 g_kh[(size_t)BATCH * NH * T_SEQ * HD];
__device__ __nv_bfloat16 g_kl[(size_t)BATCH * NH * T_SEQ * HD];
__device__ __nv_bfloat16 g_vh[(size_t)BATCH * NH * T_SEQ * HD];
__device__ __nv_bfloat16 g_vl[(size_t)BATCH * NH * T_SEQ * HD];

__device__ __nv_bfloat16 g_Ah[(size_t)M_ROWS * D_MODEL];      // GEMM activation hi
__device__ __nv_bfloat16 g_Al[(size_t)M_ROWS * D_MODEL];      // GEMM activation lo
__device__ __nv_bfloat16 g_Wth[4][(size_t)D_MODEL * D_MODEL]; // W^T hi (K-major)
__device__ __nv_bfloat16 g_Wtl[4][(size_t)D_MODEL * D_MODEL]; // W^T lo

// ---------------------------------------------------------------------------
// sm_80-class PTX helpers (compute_103-safe)
// ---------------------------------------------------------------------------
__device__ __forceinline__ uint32_t smem_u32(const void* p) {
    uint32_t a;
    asm("{ .reg .u64 t; cvta.to.shared.u64 t, %1; cvt.u32.u64 %0, t; }" : "=r"(a) : "l"(p));
    return a;
}
#define CP_ASYNC16(saddr, gptr) \
    asm volatile("cp.async.cg.shared.global [%0], [%1], 16;" \
        :: "r"(saddr), "l"(gptr) : "memory")
#define CP_COMMIT() asm volatile("cp.async.commit_group;" ::: "memory")
#define CP_WAIT(n)  asm volatile("cp.async.wait_group %0;" :: "n"(n) : "memory")

#define LDSM_X4(r0, r1, r2, r3, addr) \
    asm volatile("ldmatrix.sync.aligned.m8n8.x4.shared.b16 {%0,%1,%2,%3}, [%4];" \
        : "=r"(r0), "=r"(r1), "=r"(r2), "=r"(r3) : "r"(addr))
#define LDSM_X4T(r0, r1, r2, r3, addr) \
    asm volatile("ldmatrix.sync.aligned.m8n8.x4.trans.shared.b16 {%0,%1,%2,%3}, [%4];" \
        : "=r"(r0), "=r"(r1), "=r"(r2), "=r"(r3) : "r"(addr))

// D += A*B, m16n8k16 row.col f32.bf16.bf16.f32
#define MMA16816(d, a, b0, b1) \
    asm volatile("mma.sync.aligned.m16n8k16.row.col.f32.bf16.bf16.f32 " \
        "{%0,%1,%2,%3}, {%4,%5,%6,%7}, {%8,%9}, {%0,%1,%2,%3};" \
        : "+f"((d)[0]), "+f"((d)[1]), "+f"((d)[2]), "+f"((d)[3]) \
        : "r"((a)[0]), "r"((a)[1]), "r"((a)[2]), "r"((a)[3]), "r"(b0), "r"(b1))

struct B3 { const float* b[3]; };
struct W4 { const float* W[4]; };

__device__ __forceinline__ void split2(float a, float b,
                                       __nv_bfloat162& h, __nv_bfloat162& l) {
    __nv_bfloat16 ha = __float2bfloat16(a), hb = __float2bfloat16(b);
    h.x = ha; h.y = hb;
    l.x = __float2bfloat16(a - __bfloat162float(ha));
    l.y = __float2bfloat16(b - __bfloat162float(hb));
}

// packed variant: h/l as uint32 bf16x2 via cvt.rn.bf16x2.f32 (RN == split2;
// bit-identical results, fewer instructions)
__device__ __forceinline__ void split2p(float a, float b, uint32_t& h, uint32_t& l) {
    asm("cvt.rn.bf16x2.f32 %0, %1, %2;" : "=r"(h) : "f"(b), "f"(a));  // low=a, high=b
    const __nv_bfloat162 hv = *(const __nv_bfloat162*)&h;
    const float ra = a - __bfloat162float(hv.x);
    const float rb = b - __bfloat162float(hv.y);
    asm("cvt.rn.bf16x2.f32 %0, %1, %2;" : "=r"(l) : "f"(rb), "f"(ra));
}

// ---------------------------------------------------------------------------
// fp32 x -> bf16 hi/lo split (elementwise) into g_Ah/g_Al
// ---------------------------------------------------------------------------
__global__ __launch_bounds__(256)
void split_kernel(const float* __restrict__ xsrc)
{
    const int i = blockIdx.x * 256 + threadIdx.x;   // float4 index
    float4 v = ((const float4*)xsrc)[i];
    __nv_bfloat162 h0, l0, h1, l1;
    split2(v.x, v.y, h0, l0);
    split2(v.z, v.w, h1, l1);
    ((__nv_bfloat162*)g_Ah)[i * 2 + 0] = h0;
    ((__nv_bfloat162*)g_Ah)[i * 2 + 1] = h1;
    ((__nv_bfloat162*)g_Al)[i * 2 + 0] = l0;
    ((__nv_bfloat162*)g_Al)[i * 2 + 1] = l1;
}

// ---------------------------------------------------------------------------
// W [k,n] fp32 -> W^T [n,k] bf16 hi/lo, all 4 weights (z)
// ---------------------------------------------------------------------------
__global__ __launch_bounds__(256)
void wtrans_kernel(W4 w)
{
    __shared__ float tile[32][33];
    const int z = blockIdx.z;
    const float* __restrict__ W = w.W[z];
    const int n0 = blockIdx.x * 32, k0 = blockIdx.y * 32;
    const int tx = threadIdx.x & 31, ty = threadIdx.x >> 5;  // 32 x 8
#pragma unroll
    for (int i = 0; i < 4; i++)
        tile[ty + i * 8][tx] = W[(size_t)(k0 + ty + i * 8) * D_MODEL + n0 + tx];
    __syncthreads();
#pragma unroll
    for (int i = 0; i < 4; i++) {
        float v = tile[tx][ty + i * 8];
        __nv_bfloat16 h = __float2bfloat16(v);
        size_t idx = (size_t)(n0 + ty + i * 8) * D_MODEL + k0 + tx;
        g_Wth[z][idx] = h;
        g_Wtl[z][idx] = __float2bfloat16(v - __bfloat162float(h));
    }
}

// ---------------------------------------------------------------------------
// RAW-MMA GEMM (R13/R14 proven): C[128x128] tile + bias. Unchanged this round.
// ---------------------------------------------------------------------------
#define BK        32
#define GFLD      80                           // bytes per 32-bf16 row (padded)
#define GMAT      (128 * GFLD)                 // 10240
#define GSTG      (4 * GMAT)                   // 40960: Ah Al Bh Bl
#define GEMM_SMEM (2 * GSTG)                   // 81920 -> 2 blocks/SM
#define NCHUNKS   (D_MODEL / BK)               // 32

template <bool QKV>
__global__ __launch_bounds__(256, 2)
void mma_gemm_kernel(B3 biases, float* __restrict__ Cout)
{
    extern __shared__ char smc[];
    const uint32_t smb = smem_u32(smc);
    const int tid  = threadIdx.x;
    const int wid  = tid >> 5;
    const int lane = tid & 31;
    const int g    = lane >> 2;
    const int t    = lane & 3;

    const int z = QKV ? blockIdx.z : 3;
    const int rowBase = blockIdx.y * 128;
    const int colBase = blockIdx.x * 128;
    const float* __restrict__ bias = QKV ? biases.b[z] : biases.b[0];

    const __nv_bfloat16* __restrict__ src[4] = {
        g_Ah + (size_t)rowBase * D_MODEL,
        g_Al + (size_t)rowBase * D_MODEL,
        g_Wth[z] + (size_t)colBase * D_MODEL,
        g_Wtl[z] + (size_t)colBase * D_MODEL
    };

    const int wm = wid & 1;          // M half (64 rows)
    const int wn = wid >> 1;         // N quarter (32 cols)

    const uint32_t rA = (uint32_t)((lane & 15) * GFLD + ((lane & 16) ? 16 : 0));
    const uint32_t rB = (uint32_t)(((lane & 7) + ((lane & 16) ? 8 : 0)) * GFLD
                                   + ((lane & 8) ? 16 : 0));

    float acc[4][4][4];              // [mf][n8][4]
#pragma unroll
    for (int mf = 0; mf < 4; ++mf)
#pragma unroll
        for (int n8 = 0; n8 < 4; ++n8)
#pragma unroll
            for (int c = 0; c < 4; ++c) acc[mf][n8][c] = 0.f;

    auto load_stage = [&](int stage, int k0) {
        const uint32_t sb = smb + stage * GSTG;
#pragma unroll
        for (int mat = 0; mat < 4; ++mat) {
#pragma unroll
            for (int half = 0; half < 2; ++half) {
                const int e = tid + half * 256;      // 0..511
                const int row = e >> 2;              // 0..127
                const int c4 = e & 3;                // 16B chunk
                CP_ASYNC16(sb + (uint32_t)(mat * GMAT + row * GFLD + c4 * 16),
                           src[mat] + (size_t)row * D_MODEL + k0 + c4 * 8);
            }
        }
        CP_COMMIT();
    };

    load_stage(0, 0);

    for (int c = 0; c < NCHUNKS; ++c) {
        CP_WAIT(0);            // stage c landed
        __syncthreads();       // all warps past compute(c-1)
        if (c + 1 < NCHUNKS) load_stage((c + 1) & 1, (c + 1) * BK);

        const uint32_t sb = smb + (c & 1) * GSTG;
        const uint32_t aRow = sb + (uint32_t)(wm * 64) * GFLD + rA;
        const uint32_t bRow = sb + 2 * GMAT + (uint32_t)(wn * 32) * GFLD + rB;

#pragma unroll
        for (int ks = 0; ks < 2; ++ks) {
            const uint32_t ko = (uint32_t)(ks * 32);
            // ---- term 1: Ah x Bh ----
            uint32_t ah[4][4], bh[2][4];
#pragma unroll
            for (int mf = 0; mf < 4; ++mf)
                LDSM_X4(ah[mf][0], ah[mf][1], ah[mf][2], ah[mf][3],
                        aRow + (uint32_t)(mf * 16) * GFLD + ko);
#pragma unroll
            for (int j2 = 0; j2 < 2; ++j2)
                LDSM_X4(bh[j2][0], bh[j2][1], bh[j2][2], bh[j2][3],
                        bRow + (uint32_t)(j2 * 16) * GFLD + ko);
#pragma unroll
            for (int mf = 0; mf < 4; ++mf)
#pragma unroll
                for (int j2 = 0; j2 < 2; ++j2) {
                    MMA16816(acc[mf][2 * j2],     ah[mf], bh[j2][0], bh[j2][1]);
                    MMA16816(acc[mf][2 * j2 + 1], ah[mf], bh[j2][2], bh[j2][3]);
                }
            // ---- term 2: Al x Bh ----
            uint32_t al[4][4];
#pragma unroll
            for (int mf = 0; mf < 4; ++mf)
                LDSM_X4(al[mf][0], al[mf][1], al[mf][2], al[mf][3],
                        aRow + GMAT + (uint32_t)(mf * 16) * GFLD + ko);
#pragma unroll
            for (int mf = 0; mf < 4; ++mf)
#pragma unroll
                for (int j2 = 0; j2 < 2; ++j2) {
                    MMA16816(acc[mf][2 * j2],     al[mf], bh[j2][0], bh[j2][1]);
                    MMA16816(acc[mf][2 * j2 + 1], al[mf], bh[j2][2], bh[j2][3]);
                }
            // ---- term 3: Ah x Bl ----
            uint32_t bl[2][4];
#pragma unroll
            for (int j2 = 0; j2 < 2; ++j2)
                LDSM_X4(bl[j2][0], bl[j2][1], bl[j2][2], bl[j2][3],
                        bRow + GMAT + (uint32_t)(j2 * 16) * GFLD + ko);
#pragma unroll
            for (int mf = 0; mf < 4; ++mf)
#pragma unroll
                for (int j2 = 0; j2 < 2; ++j2) {
                    MMA16816(acc[mf][2 * j2],     ah[mf], bl[j2][0], bl[j2][1]);
                    MMA16816(acc[mf][2 * j2 + 1], ah[mf], bl[j2][2], bl[j2][3]);
                }
        }
    }

    // ---- direct-register epilogue (flash-O layout), no smem staging ----
#pragma unroll
    for (int mf = 0; mf < 4; ++mf) {
        const int row0 = rowBase + wm * 64 + mf * 16 + g;
#pragma unroll
        for (int n8 = 0; n8 < 4; ++n8) {
            const int col = colBase + wn * 32 + n8 * 8 + 2 * t;
            const float bx = __ldg(&bias[col]);
            const float by = __ldg(&bias[col + 1]);
            float2 v0 = { acc[mf][n8][0] + bx, acc[mf][n8][1] + by };
            float2 v1 = { acc[mf][n8][2] + bx, acc[mf][n8][3] + by };
            if (QKV) {
                __nv_bfloat16 *dh, *dl;
                if (z == 0)      { dh = g_qh; dl = g_ql; }
                else if (z == 1) { dh = g_kh; dl = g_kl; }
                else             { dh = g_vh; dl = g_vl; }
                const int hd = col & 63;
                const int hh = col >> 6;
#pragma unroll
                for (int r = 0; r < 2; ++r) {
                    const int row = row0 + r * 8;
                    const int bh_ = (row >> 11) * NH + hh;
                    const int tt  = row & 2047;
                    const size_t o = ((size_t)bh_ * T_SEQ + tt) * HD + hd;
                    __nv_bfloat162 h2, l2;
                    split2(r ? v1.x : v0.x, r ? v1.y : v0.y, h2, l2);
                    *(__nv_bfloat162*)(dh + o) = h2;
                    *(__nv_bfloat162*)(dl + o) = l2;
                }
            } else {
                *(float2*)&Cout[(size_t)row0 * D_MODEL + col] = v0;
                *(float2*)&Cout[(size_t)(row0 + 8) * D_MODEL + col] = v1;
            }
        }
    }
}

// ---------------------------------------------------------------------------
// Flash v5.3: as R12/R14 flash (proven rel_err 1.663709e-05) with two
// scalar-phase optimizations, arithmetic unchanged (bit-identical):
//  1. Causal mask evaluated ONLY on the 2 diagonal tiles (kt >= 2*qt);
//     bulk tiles (kt < 2*qt) have all keys <= min query row -> no compares.
//  2. P hi/lo packing via single-instruction cvt.rn.bf16x2.f32 (split2p).
// ---------------------------------------------------------------------------
#define QTQ      128
#define KTK      64
#define FL_THR   256
#define FLD      144
#define MAT9     (KTK * FLD)                   // 9216
#define STG_B    (4 * MAT9)                    // 36864
#define FL_SMEM  (3 * STG_B)                   // 110592

__global__ __launch_bounds__(FL_THR, 2)
void flash_fa2_kernel()
{
    extern __shared__ char smf[];
    const uint32_t smb = smem_u32(smf);

    const int tid  = threadIdx.x;
    const int w    = tid >> 5;
    const int lane = tid & 31;
    const int g    = lane >> 2;
    const int t    = lane & 3;
    const int bh   = blockIdx.y;
    const int qt   = gridDim.x - 1 - blockIdx.x;
    const int ktmax = 2 * qt + 1;
    const int bulk  = 2 * qt;                  // tiles < bulk need no mask

    const size_t base = (size_t)bh * T_SEQ * HD;

    const uint32_t rK = (uint32_t)(((lane & 7) + ((lane & 16) ? 8 : 0)) * FLD
                                   + ((lane & 8) ? 16 : 0));
    const uint32_t rV = (uint32_t)(((lane & 7) + ((lane & 8) ? 8 : 0)) * FLD
                                   + ((lane & 16) ? 16 : 0));
    const uint32_t rQ = (uint32_t)((lane & 15) * FLD + ((lane & 16) ? 16 : 0));

    {
        const __nv_bfloat16* qsrc[2] = { g_qh + base + (size_t)qt * QTQ * HD,
                                         g_ql + base + (size_t)qt * QTQ * HD };
#pragma unroll
        for (int m = 0; m < 2; ++m) {
            const uint32_t dst = smb + 2 * STG_B + m * (QTQ * FLD);
#pragma unroll
            for (int it = 0; it < 4; ++it) {
                const int e = tid + it * FL_THR;
                const int r = e >> 3, s = e & 7;
                CP_ASYNC16(dst + (uint32_t)(r * FLD + s * 16),
                           qsrc[m] + (size_t)r * HD + s * 8);
            }
        }
        CP_COMMIT();
    }
    auto prefetch = [&](int kt_, int stage) {
        const uint32_t sb = smb + stage * STG_B;
        const size_t kb = base + (size_t)kt_ * KTK * HD;
        const __nv_bfloat16* gsrc[4] = { g_kh + kb, g_kl + kb, g_vh + kb, g_vl + kb };
#pragma unroll
        for (int mat = 0; mat < 4; ++mat) {
#pragma unroll
            for (int it = 0; it < 2; ++it) {
                const int e = tid + it * FL_THR;
                const int r = e >> 3, s = e & 7;
                CP_ASYNC16(sb + (uint32_t)(mat * MAT9 + r * FLD + s * 16),
                           gsrc[mat] + (size_t)r * HD + s * 8);
            }
        }
        CP_COMMIT();
    };
    prefetch(0, 0);
    CP_WAIT(1);
    __syncthreads();

    uint32_t qhf[4][4], qlf[4][4];
    {
        const uint32_t q2 = smb + 2 * STG_B + (uint32_t)(w * 16) * FLD + rQ;
#pragma unroll
        for (int kg = 0; kg < 4; ++kg) {
            LDSM_X4(qhf[kg][0], qhf[kg][1], qhf[kg][2], qhf[kg][3], q2 + kg * 32);
            LDSM_X4(qlf[kg][0], qlf[kg][1], qlf[kg][2], qlf[kg][3], q2 + 18432u + kg * 32);
        }
    }
    if (1 <= ktmax) prefetch(1, 1); else CP_COMMIT();

    float O[8][4];
#pragma unroll
    for (int j = 0; j < 8; ++j)
#pragma unroll
        for (int c = 0; c < 4; ++c) O[j][c] = 0.f;
    float lg = 0.f, lg8 = 0.f;
    const int rq0 = qt * QTQ + w * 16 + g;
    const int rq1 = rq0 + 8;

    for (int kt = 0; kt <= ktmax; ++kt) {
        CP_WAIT(1);
        __syncthreads();
        if (kt + 2 <= ktmax) prefetch(kt + 2, (kt + 2) % 3); else CP_COMMIT();

        const uint32_t sb = smb + (kt % 3) * STG_B;

        float S[8][4];
#pragma unroll
        for (int j = 0; j < 8; ++j)
#pragma unroll
            for (int c = 0; c < 4; ++c) S[j][c] = 0.f;

#pragma unroll
        for (int kg = 0; kg < 4; ++kg) {
#pragma unroll
            for (int jj = 0; jj < 4; ++jj) {
                const uint32_t ka = sb + (uint32_t)(jj * 2304 + kg * 32) + rK;
                uint32_t kh0, kh1, kh2, kh3, kl0, kl1, kl2, kl3;
                LDSM_X4(kh0, kh1, kh2, kh3, ka);
                LDSM_X4(kl0, kl1, kl2, kl3, ka + MAT9);
                MMA16816(S[2 * jj],     qhf[kg], kh0, kh1);
                MMA16816(S[2 * jj + 1], qhf[kg], kh2, kh3);
                MMA16816(S[2 * jj],     qlf[kg], kh0, kh1);
                MMA16816(S[2 * jj + 1], qlf[kg], kh2, kh3);
                MMA16816(S[2 * jj],     qhf[kg], kl0, kl1);
                MMA16816(S[2 * jj + 1], qhf[kg], kl2, kl3);
            }
        }

        // ---- scalar phase: exp + l; mask only on diagonal tiles ----
        if (kt < bulk) {
#pragma unroll
            for (int j = 0; j < 8; ++j) {
                S[j][0] = __expf(S[j][0] * 0.125f);
                S[j][1] = __expf(S[j][1] * 0.125f);
                S[j][2] = __expf(S[j][2] * 0.125f);
                S[j][3] = __expf(S[j][3] * 0.125f);
                lg  += S[j][0] + S[j][1];
                lg8 += S[j][2] + S[j][3];
            }
        } else {
#pragma unroll
            for (int j = 0; j < 8; ++j) {
                const int kb = kt * KTK + 8 * j + 2 * t;
                S[j][0] = (kb     <= rq0) ? __expf(S[j][0] * 0.125f) : 0.f;
                S[j][1] = (kb + 1 <= rq0) ? __expf(S[j][1] * 0.125f) : 0.f;
                S[j][2] = (kb     <= rq1) ? __expf(S[j][2] * 0.125f) : 0.f;
                S[j][3] = (kb + 1 <= rq1) ? __expf(S[j][3] * 0.125f) : 0.f;
                lg  += S[j][0] + S[j][1];
                lg8 += S[j][2] + S[j][3];
            }
        }

#pragma unroll
        for (int kg = 0; kg < 4; ++kg) {
            uint32_t ph[4], pl[4];
            split2p(S[2 * kg][0],     S[2 * kg][1],     ph[0], pl[0]);
            split2p(S[2 * kg][2],     S[2 * kg][3],     ph[1], pl[1]);
            split2p(S[2 * kg + 1][0], S[2 * kg + 1][1], ph[2], pl[2]);
            split2p(S[2 * kg + 1][2], S[2 * kg + 1][3], ph[3], pl[3]);
#pragma unroll
            for (int jj = 0; jj < 4; ++jj) {
                const uint32_t va = sb + (uint32_t)(2 * MAT9 + kg * 2304 + jj * 32) + rV;
                uint32_t vh0, vh1, vh2, vh3, vl0, vl1, vl2, vl3;
                LDSM_X4T(vh0, vh1, vh2, vh3, va);
                LDSM_X4T(vl0, vl1, vl2, vl3, va + MAT9);
                MMA16816(O[2 * jj],     ph, vh0, vh1);
                MMA16816(O[2 * jj + 1], ph, vh2, vh3);
                MMA16816(O[2 * jj],     pl, vh0, vh1);
                MMA16816(O[2 * jj + 1], pl, vh2, vh3);
                MMA16816(O[2 * jj],     ph, vl0, vl1);
                MMA16816(O[2 * jj + 1], ph, vl2, vl3);
            }
        }
    }

    lg  += __shfl_xor_sync(0xffffffffu, lg, 1);
    lg  += __shfl_xor_sync(0xffffffffu, lg, 2);
    lg8 += __shfl_xor_sync(0xffffffffu, lg8, 1);
    lg8 += __shfl_xor_sync(0xffffffffu, lg8, 2);
    const float li0 = 1.0f / lg;
    const float li8 = 1.0f / lg8;

    const int b = bh >> 4, h = bh & 15;
    const int rq0g = qt * QTQ + w * 16 + g;
    const size_t ob0 = ((size_t)(b * T_SEQ + rq0g)) * D_MODEL + h * HD;
    const size_t ob1 = ((size_t)(b * T_SEQ + rq0g + 8)) * D_MODEL + h * HD;
#pragma unroll
    for (int j = 0; j < 8; ++j) {
        const int col = 8 * j + 2 * t;
        __nv_bfloat162 h2, l2;
        split2(O[j][0] * li0, O[j][1] * li0, h2, l2);
        *(__nv_bfloat162*)&g_Ah[ob0 + col] = h2;
        *(__nv_bfloat162*)&g_Al[ob0 + col] = l2;
        split2(O[j][2] * li8, O[j][3] * li8, h2, l2);
        *(__nv_bfloat162*)&g_Ah[ob1 + col] = h2;
        *(__nv_bfloat162*)&g_Al[ob1 + col] = l2;
    }
}

// ---------------------------------------------------------------------------
extern "C" void kernel_launch(void* const* d_in, const int* in_sizes, int n_in,
                              void* d_out, int out_size)
{
    (void)in_sizes; (void)n_in; (void)out_size;
    const float* x  = (const float*)d_in[0];
    const float* Wq = (const float*)d_in[1];
    const float* bq = (const float*)d_in[2];
    const float* Wk = (const float*)d_in[3];
    const float* bk = (const float*)d_in[4];
    const float* Wv = (const float*)d_in[5];
    const float* bv = (const float*)d_in[6];
    const float* Wo = (const float*)d_in[7];
    const float* bo = (const float*)d_in[8];
    float* out = (float*)d_out;

    cudaFuncSetAttribute(mma_gemm_kernel<true>,
                         cudaFuncAttributeMaxDynamicSharedMemorySize, GEMM_SMEM);
    cudaFuncSetAttribute(mma_gemm_kernel<false>,
                         cudaFuncAttributeMaxDynamicSharedMemorySize, GEMM_SMEM);
    cudaFuncSetAttribute(flash_fa2_kernel,
                         cudaFuncAttributeMaxDynamicSharedMemorySize, FL_SMEM);

    // 0) split x -> g_Ah/g_Al; transpose+split weights
    split_kernel<<<M_ROWS * D_MODEL / 1024, 256>>>(x);
    W4 w4; w4.W[0] = Wq; w4.W[1] = Wk; w4.W[2] = Wv; w4.W[3] = Wo;
    wtrans_kernel<<<dim3(32, 32, 4), 256>>>(w4);

    // 1) QKV projections (raw-mma GEMM) -> bf16 hi/lo Q/K/V [bh][t][hd]
    B3 bqkv; bqkv.b[0] = bq; bqkv.b[1] = bk; bqkv.b[2] = bv;
    mma_gemm_kernel<true><<<dim3(D_MODEL / 128, M_ROWS / 128, 3), 256, GEMM_SMEM>>>(bqkv, nullptr);

    // 2) causal flash v5.3 (diagonal-only masking, packed P cvt) -> g_Ah/g_Al
    flash_fa2_kernel<<<dim3(T_SEQ / QTQ, BATCH * NH), FL_THR, FL_SMEM>>>();

    // 3) O projection (raw-mma GEMM) -> d_out
    B3 bout; bout.b[0] = bo; bout.b[1] = bo; bout.b[2] = bo;
    mma_gemm_kernel<false><<<dim3(D_MODEL / 128, M_ROWS / 128, 1), 256, GEMM_SMEM>>>(bout, out);
}

// round 16
// speedup vs baseline: 1.1268x; 1.0073x over previous
#include <cuda_runtime.h>
#include <cuda_bf16.h>
#include <cstdint>

// Problem constants
#define BATCH   4
#define T_SEQ   2048
#define D_MODEL 1024
#define NH      16
#define HD      64
#define M_ROWS  (BATCH * T_SEQ)   // 8192

// exp(q·k/8) == 2^((q*QSCALE)·k); Q pre-scaled in the QKV epilogue
#define QSCALE  0.18033688011112042f   // log2(e)/8

// ---------------------------------------------------------------------------
// Scratch (device globals; referenced ONLY inside device code — see R5 note)
// ---------------------------------------------------------------------------
__device__ __nv_bfloat16 g_qh[(size_t)BATCH * NH * T_SEQ * HD];  // Q hi (pre-scaled)
__device__ __nv_bfloat16 g_ql[(size_t)BATCH * NH * T_SEQ * HD];
__device__ __nv_bfloat16 g_kh[(size_t)BATCH * NH * T_SEQ * HD];
__device__ __nv_bfloat16 g_kl[(size_t)BATCH * NH * T_SEQ * HD];
__device__ __nv_bfloat16 g_vh[(size_t)BATCH * NH * T_SEQ * HD];
__device__ __nv_bfloat16 g_vl[(size_t)BATCH * NH * T_SEQ * HD];

__device__ __nv_bfloat16 g_Ah[(size_t)M_ROWS * D_MODEL];      // GEMM activation hi
__device__ __nv_bfloat16 g_Al[(size_t)M_ROWS * D_MODEL];      // GEMM activation lo
__device__ __nv_bfloat16 g_Wth[4][(size_t)D_MODEL * D_MODEL]; // W^T hi (K-major)
__device__ __nv_bfloat16 g_Wtl[4][(size_t)D_MODEL * D_MODEL]; // W^T lo

// ---------------------------------------------------------------------------
// sm_80-class PTX helpers (compute_103-safe)
// ---------------------------------------------------------------------------
__device__ __forceinline__ uint32_t smem_u32(const void* p) {
    uint32_t a;
    asm("{ .reg .u64 t; cvta.to.shared.u64 t, %1; cvt.u32.u64 %0, t; }" : "=r"(a) : "l"(p));
    return a;
}
#define CP_ASYNC16(saddr, gptr) \
    asm volatile("cp.async.cg.shared.global [%0], [%1], 16;" \
        :: "r"(saddr), "l"(gptr) : "memory")
#define CP_COMMIT() asm volatile("cp.async.commit_group;" ::: "memory")
#define CP_WAIT(n)  asm volatile("cp.async.wait_group %0;" :: "n"(n) : "memory")

#define LDSM_X4(r0, r1, r2, r3, addr) \
    asm volatile("ldmatrix.sync.aligned.m8n8.x4.shared.b16 {%0,%1,%2,%3}, [%4];" \
        : "=r"(r0), "=r"(r1), "=r"(r2), "=r"(r3) : "r"(addr))
#define LDSM_X4T(r0, r1, r2, r3, addr) \
    asm volatile("ldmatrix.sync.aligned.m8n8.x4.trans.shared.b16 {%0,%1,%2,%3}, [%4];" \
        : "=r"(r0), "=r"(r1), "=r"(r2), "=r"(r3) : "r"(addr))

// D += A*B, m16n8k16 row.col f32.bf16.bf16.f32
#define MMA16816(d, a, b0, b1) \
    asm volatile("mma.sync.aligned.m16n8k16.row.col.f32.bf16.bf16.f32 " \
        "{%0,%1,%2,%3}, {%4,%5,%6,%7}, {%8,%9}, {%0,%1,%2,%3};" \
        : "+f"((d)[0]), "+f"((d)[1]), "+f"((d)[2]), "+f"((d)[3]) \
        : "r"((a)[0]), "r"((a)[1]), "r"((a)[2]), "r"((a)[3]), "r"(b0), "r"(b1))

struct B3 { const float* b[3]; };
struct W4 { const float* W[4]; };

__device__ __forceinline__ float ex2a(float x) {
    float r;
    asm("ex2.approx.f32 %0, %1;" : "=f"(r) : "f"(x));
    return r;
}

__device__ __forceinline__ void split2(float a, float b,
                                       __nv_bfloat162& h, __nv_bfloat162& l) {
    __nv_bfloat16 ha = __float2bfloat16(a), hb = __float2bfloat16(b);
    h.x = ha; h.y = hb;
    l.x = __float2bfloat16(a - __bfloat162float(ha));
    l.y = __float2bfloat16(b - __bfloat162float(hb));
}

// packed variant: h/l as uint32 bf16x2 via cvt.rn.bf16x2.f32
__device__ __forceinline__ void split2p(float a, float b, uint32_t& h, uint32_t& l) {
    asm("cvt.rn.bf16x2.f32 %0, %1, %2;" : "=r"(h) : "f"(b), "f"(a));  // low=a, high=b
    const __nv_bfloat162 hv = *(const __nv_bfloat162*)&h;
    const float ra = a - __bfloat162float(hv.x);
    const float rb = b - __bfloat162float(hv.y);
    asm("cvt.rn.bf16x2.f32 %0, %1, %2;" : "=r"(l) : "f"(rb), "f"(ra));
}

// ---------------------------------------------------------------------------
// fp32 x -> bf16 hi/lo split (elementwise) into g_Ah/g_Al
// ---------------------------------------------------------------------------
__global__ __launch_bounds__(256)
void split_kernel(const float* __restrict__ xsrc)
{
    const int i = blockIdx.x * 256 + threadIdx.x;   // float4 index
    float4 v = ((const float4*)xsrc)[i];
    __nv_bfloat162 h0, l0, h1, l1;
    split2(v.x, v.y, h0, l0);
    split2(v.z, v.w, h1, l1);
    ((__nv_bfloat162*)g_Ah)[i * 2 + 0] = h0;
    ((__nv_bfloat162*)g_Ah)[i * 2 + 1] = h1;
    ((__nv_bfloat162*)g_Al)[i * 2 + 0] = l0;
    ((__nv_bfloat162*)g_Al)[i * 2 + 1] = l1;
}

// ---------------------------------------------------------------------------
// W [k,n] fp32 -> W^T [n,k] bf16 hi/lo, all 4 weights (z)
// ---------------------------------------------------------------------------
__global__ __launch_bounds__(256)
void wtrans_kernel(W4 w)
{
    __shared__ float tile[32][33];
    const int z = blockIdx.z;
    const float* __restrict__ W = w.W[z];
    const int n0 = blockIdx.x * 32, k0 = blockIdx.y * 32;
    const int tx = threadIdx.x & 31, ty = threadIdx.x >> 5;  // 32 x 8
#pragma unroll
    for (int i = 0; i < 4; i++)
        tile[ty + i * 8][tx] = W[(size_t)(k0 + ty + i * 8) * D_MODEL + n0 + tx];
    __syncthreads();
#pragma unroll
    for (int i = 0; i < 4; i++) {
        float v = tile[tx][ty + i * 8];
        __nv_bfloat16 h = __float2bfloat16(v);
        size_t idx = (size_t)(n0 + ty + i * 8) * D_MODEL + k0 + tx;
        g_Wth[z][idx] = h;
        g_Wtl[z][idx] = __float2bfloat16(v - __bfloat162float(h));
    }
}

// ---------------------------------------------------------------------------
// RAW-MMA GEMM (R13/R14 proven): C[128x128] tile + bias.
// R16: QKV z==0 epilogue pre-scales Q by QSCALE (softmax scale folding).
// ---------------------------------------------------------------------------
#define BK        32
#define GFLD      80                           // bytes per 32-bf16 row (padded)
#define GMAT      (128 * GFLD)                 // 10240
#define GSTG      (4 * GMAT)                   // 40960: Ah Al Bh Bl
#define GEMM_SMEM (2 * GSTG)                   // 81920 -> 2 blocks/SM
#define NCHUNKS   (D_MODEL / BK)               // 32

template <bool QKV>
__global__ __launch_bounds__(256, 2)
void mma_gemm_kernel(B3 biases, float* __restrict__ Cout)
{
    extern __shared__ char smc[];
    const uint32_t smb = smem_u32(smc);
    const int tid  = threadIdx.x;
    const int wid  = tid >> 5;
    const int lane = tid & 31;
    const int g    = lane >> 2;
    const int t    = lane & 3;

    const int z = QKV ? blockIdx.z : 3;
    const int rowBase = blockIdx.y * 128;
    const int colBase = blockIdx.x * 128;
    const float* __restrict__ bias = QKV ? biases.b[z] : biases.b[0];

    const __nv_bfloat16* __restrict__ src[4] = {
        g_Ah + (size_t)rowBase * D_MODEL,
        g_Al + (size_t)rowBase * D_MODEL,
        g_Wth[z] + (size_t)colBase * D_MODEL,
        g_Wtl[z] + (size_t)colBase * D_MODEL
    };

    const int wm = wid & 1;          // M half (64 rows)
    const int wn = wid >> 1;         // N quarter (32 cols)

    const uint32_t rA = (uint32_t)((lane & 15) * GFLD + ((lane & 16) ? 16 : 0));
    const uint32_t rB = (uint32_t)(((lane & 7) + ((lane & 16) ? 8 : 0)) * GFLD
                                   + ((lane & 8) ? 16 : 0));

    float acc[4][4][4];              // [mf][n8][4]
#pragma unroll
    for (int mf = 0; mf < 4; ++mf)
#pragma unroll
        for (int n8 = 0; n8 < 4; ++n8)
#pragma unroll
            for (int c = 0; c < 4; ++c) acc[mf][n8][c] = 0.f;

    auto load_stage = [&](int stage, int k0) {
        const uint32_t sb = smb + stage * GSTG;
#pragma unroll
        for (int mat = 0; mat < 4; ++mat) {
#pragma unroll
            for (int half = 0; half < 2; ++half) {
                const int e = tid + half * 256;      // 0..511
                const int row = e >> 2;              // 0..127
                const int c4 = e & 3;                // 16B chunk
                CP_ASYNC16(sb + (uint32_t)(mat * GMAT + row * GFLD + c4 * 16),
                           src[mat] + (size_t)row * D_MODEL + k0 + c4 * 8);
            }
        }
        CP_COMMIT();
    };

    load_stage(0, 0);

    for (int c = 0; c < NCHUNKS; ++c) {
        CP_WAIT(0);            // stage c landed
        __syncthreads();       // all warps past compute(c-1)
        if (c + 1 < NCHUNKS) load_stage((c + 1) & 1, (c + 1) * BK);

        const uint32_t sb = smb + (c & 1) * GSTG;
        const uint32_t aRow = sb + (uint32_t)(wm * 64) * GFLD + rA;
        const uint32_t bRow = sb + 2 * GMAT + (uint32_t)(wn * 32) * GFLD + rB;

#pragma unroll
        for (int ks = 0; ks < 2; ++ks) {
            const uint32_t ko = (uint32_t)(ks * 32);
            // ---- term 1: Ah x Bh ----
            uint32_t ah[4][4], bh[2][4];
#pragma unroll
            for (int mf = 0; mf < 4; ++mf)
                LDSM_X4(ah[mf][0], ah[mf][1], ah[mf][2], ah[mf][3],
                        aRow + (uint32_t)(mf * 16) * GFLD + ko);
#pragma unroll
            for (int j2 = 0; j2 < 2; ++j2)
                LDSM_X4(bh[j2][0], bh[j2][1], bh[j2][2], bh[j2][3],
                        bRow + (uint32_t)(j2 * 16) * GFLD + ko);
#pragma unroll
            for (int mf = 0; mf < 4; ++mf)
#pragma unroll
                for (int j2 = 0; j2 < 2; ++j2) {
                    MMA16816(acc[mf][2 * j2],     ah[mf], bh[j2][0], bh[j2][1]);
                    MMA16816(acc[mf][2 * j2 + 1], ah[mf], bh[j2][2], bh[j2][3]);
                }
            // ---- term 2: Al x Bh ----
            uint32_t al[4][4];
#pragma unroll
            for (int mf = 0; mf < 4; ++mf)
                LDSM_X4(al[mf][0], al[mf][1], al[mf][2], al[mf][3],
                        aRow + GMAT + (uint32_t)(mf * 16) * GFLD + ko);
#pragma unroll
            for (int mf = 0; mf < 4; ++mf)
#pragma unroll
                for (int j2 = 0; j2 < 2; ++j2) {
                    MMA16816(acc[mf][2 * j2],     al[mf], bh[j2][0], bh[j2][1]);
                    MMA16816(acc[mf][2 * j2 + 1], al[mf], bh[j2][2], bh[j2][3]);
                }
            // ---- term 3: Ah x Bl ----
            uint32_t bl[2][4];
#pragma unroll
            for (int j2 = 0; j2 < 2; ++j2)
                LDSM_X4(bl[j2][0], bl[j2][1], bl[j2][2], bl[j2][3],
                        bRow + GMAT + (uint32_t)(j2 * 16) * GFLD + ko);
#pragma unroll
            for (int mf = 0; mf < 4; ++mf)
#pragma unroll
                for (int j2 = 0; j2 < 2; ++j2) {
                    MMA16816(acc[mf][2 * j2],     ah[mf], bl[j2][0], bl[j2][1]);
                    MMA16816(acc[mf][2 * j2 + 1], ah[mf], bl[j2][2], bl[j2][3]);
                }
        }
    }

    // ---- direct-register epilogue (flash-O layout), no smem staging ----
    const float osc = (QKV && z == 0) ? QSCALE : 1.0f;   // fold softmax scale into Q
#pragma unroll
    for (int mf = 0; mf < 4; ++mf) {
        const int row0 = rowBase + wm * 64 + mf * 16 + g;
#pragma unroll
        for (int n8 = 0; n8 < 4; ++n8) {
            const int col = colBase + wn * 32 + n8 * 8 + 2 * t;
            const float bx = __ldg(&bias[col]);
            const float by = __ldg(&bias[col + 1]);
            float2 v0 = { (acc[mf][n8][0] + bx) * osc, (acc[mf][n8][1] + by) * osc };
            float2 v1 = { (acc[mf][n8][2] + bx) * osc, (acc[mf][n8][3] + by) * osc };
            if (QKV) {
                __nv_bfloat16 *dh, *dl;
                if (z == 0)      { dh = g_qh; dl = g_ql; }
                else if (z == 1) { dh = g_kh; dl = g_kl; }
                else             { dh = g_vh; dl = g_vl; }
                const int hd = col & 63;
                const int hh = col >> 6;
#pragma unroll
                for (int r = 0; r < 2; ++r) {
                    const int row = row0 + r * 8;
                    const int bh_ = (row >> 11) * NH + hh;
                    const int tt  = row & 2047;
                    const size_t o = ((size_t)bh_ * T_SEQ + tt) * HD + hd;
                    __nv_bfloat162 h2, l2;
                    split2(r ? v1.x : v0.x, r ? v1.y : v0.y, h2, l2);
                    *(__nv_bfloat162*)(dh + o) = h2;
                    *(__nv_bfloat162*)(dl + o) = l2;
                }
            } else {
                *(float2*)&Cout[(size_t)row0 * D_MODEL + col] = v0;
                *(float2*)&Cout[(size_t)(row0 + 8) * D_MODEL + col] = v1;
            }
        }
    }
}

// ---------------------------------------------------------------------------
// Flash v5.4: as R15 (proven) with
//  1. bare ex2.approx per score (scale pre-folded into Q at GEMM epilogue)
//  2. exp/lg computed INSIDE the kg loop -> scalar work interleaved between
//     PV MMA runs (no block-wide all-scalar window)
// ---------------------------------------------------------------------------
#define QTQ      128
#define KTK      64
#define FL_THR   256
#define FLD      144
#define MAT9     (KTK * FLD)                   // 9216
#define STG_B    (4 * MAT9)                    // 36864
#define FL_SMEM  (3 * STG_B)                   // 110592

// per-kg body: exp+lg (masked or not), pack P, PV MMAs
#define FLASH_KG_BODY(MASKED)                                                 \
_Pragma("unroll")                                                             \
    for (int kg = 0; kg < 4; ++kg) {                                          \
_Pragma("unroll")                                                             \
        for (int jj2 = 0; jj2 < 2; ++jj2) {                                   \
            const int j = 2 * kg + jj2;                                       \
            if (MASKED) {                                                     \
                const int kb = kt * KTK + 8 * j + 2 * t;                      \
                S[j][0] = (kb     <= rq0) ? ex2a(S[j][0]) : 0.f;              \
                S[j][1] = (kb + 1 <= rq0) ? ex2a(S[j][1]) : 0.f;              \
                S[j][2] = (kb     <= rq1) ? ex2a(S[j][2]) : 0.f;              \
                S[j][3] = (kb + 1 <= rq1) ? ex2a(S[j][3]) : 0.f;              \
            } else {                                                          \
                S[j][0] = ex2a(S[j][0]);                                      \
                S[j][1] = ex2a(S[j][1]);                                      \
                S[j][2] = ex2a(S[j][2]);                                      \
                S[j][3] = ex2a(S[j][3]);                                      \
            }                                                                 \
            lg  += S[j][0] + S[j][1];                                         \
            lg8 += S[j][2] + S[j][3];                                         \
        }                                                                     \
        uint32_t ph[4], pl[4];                                                \
        split2p(S[2 * kg][0],     S[2 * kg][1],     ph[0], pl[0]);            \
        split2p(S[2 * kg][2],     S[2 * kg][3],     ph[1], pl[1]);            \
        split2p(S[2 * kg + 1][0], S[2 * kg + 1][1], ph[2], pl[2]);            \
        split2p(S[2 * kg + 1][2], S[2 * kg + 1][3], ph[3], pl[3]);            \
_Pragma("unroll")                                                             \
        for (int jj = 0; jj < 4; ++jj) {                                      \
            const uint32_t va = sb + (uint32_t)(2 * MAT9 + kg * 2304 + jj * 32) + rV; \
            uint32_t vh0, vh1, vh2, vh3, vl0, vl1, vl2, vl3;                  \
            LDSM_X4T(vh0, vh1, vh2, vh3, va);                                 \
            LDSM_X4T(vl0, vl1, vl2, vl3, va + MAT9);                          \
            MMA16816(O[2 * jj],     ph, vh0, vh1);                            \
            MMA16816(O[2 * jj + 1], ph, vh2, vh3);                            \
            MMA16816(O[2 * jj],     pl, vh0, vh1);                            \
            MMA16816(O[2 * jj + 1], pl, vh2, vh3);                            \
            MMA16816(O[2 * jj],     ph, vl0, vl1);                            \
            MMA16816(O[2 * jj + 1], ph, vl2, vl3);                            \
        }                                                                     \
    }

__global__ __launch_bounds__(FL_THR, 2)
void flash_fa2_kernel()
{
    extern __shared__ char smf[];
    const uint32_t smb = smem_u32(smf);

    const int tid  = threadIdx.x;
    const int w    = tid >> 5;
    const int lane = tid & 31;
    const int g    = lane >> 2;
    const int t    = lane & 3;
    const int bh   = blockIdx.y;
    const int qt   = gridDim.x - 1 - blockIdx.x;
    const int ktmax = 2 * qt + 1;
    const int bulk  = 2 * qt;                  // tiles < bulk need no mask

    const size_t base = (size_t)bh * T_SEQ * HD;

    const uint32_t rK = (uint32_t)(((lane & 7) + ((lane & 16) ? 8 : 0)) * FLD
                                   + ((lane & 8) ? 16 : 0));
    const uint32_t rV = (uint32_t)(((lane & 7) + ((lane & 8) ? 8 : 0)) * FLD
                                   + ((lane & 16) ? 16 : 0));
    const uint32_t rQ = (uint32_t)((lane & 15) * FLD + ((lane & 16) ? 16 : 0));

    {
        const __nv_bfloat16* qsrc[2] = { g_qh + base + (size_t)qt * QTQ * HD,
                                         g_ql + base + (size_t)qt * QTQ * HD };
#pragma unroll
        for (int m = 0; m < 2; ++m) {
            const uint32_t dst = smb + 2 * STG_B + m * (QTQ * FLD);
#pragma unroll
            for (int it = 0; it < 4; ++it) {
                const int e = tid + it * FL_THR;
                const int r = e >> 3, s = e & 7;
                CP_ASYNC16(dst + (uint32_t)(r * FLD + s * 16),
                           qsrc[m] + (size_t)r * HD + s * 8);
            }
        }
        CP_COMMIT();
    }
    auto prefetch = [&](int kt_, int stage) {
        const uint32_t sb = smb + stage * STG_B;
        const size_t kb = base + (size_t)kt_ * KTK * HD;
        const __nv_bfloat16* gsrc[4] = { g_kh + kb, g_kl + kb, g_vh + kb, g_vl + kb };
#pragma unroll
        for (int mat = 0; mat < 4; ++mat) {
#pragma unroll
            for (int it = 0; it < 2; ++it) {
                const int e = tid + it * FL_THR;
                const int r = e >> 3, s = e & 7;
                CP_ASYNC16(sb + (uint32_t)(mat * MAT9 + r * FLD + s * 16),
                           gsrc[mat] + (size_t)r * HD + s * 8);
            }
        }
        CP_COMMIT();
    };
    prefetch(0, 0);
    CP_WAIT(1);
    __syncthreads();

    uint32_t qhf[4][4], qlf[4][4];
    {
        const uint32_t q2 = smb + 2 * STG_B + (uint32_t)(w * 16) * FLD + rQ;
#pragma unroll
        for (int kg = 0; kg < 4; ++kg) {
            LDSM_X4(qhf[kg][0], qhf[kg][1], qhf[kg][2], qhf[kg][3], q2 + kg * 32);
            LDSM_X4(qlf[kg][0], qlf[kg][1], qlf[kg][2], qlf[kg][3], q2 + 18432u + kg * 32);
        }
    }
    if (1 <= ktmax) prefetch(1, 1); else CP_COMMIT();

    float O[8][4];
#pragma unroll
    for (int j = 0; j < 8; ++j)
#pragma unroll
        for (int c = 0; c < 4; ++c) O[j][c] = 0.f;
    float lg = 0.f, lg8 = 0.f;
    const int rq0 = qt * QTQ + w * 16 + g;
    const int rq1 = rq0 + 8;

    for (int kt = 0; kt <= ktmax; ++kt) {
        CP_WAIT(1);
        __syncthreads();
        if (kt + 2 <= ktmax) prefetch(kt + 2, (kt + 2) % 3); else CP_COMMIT();

        const uint32_t sb = smb + (kt % 3) * STG_B;

        float S[8][4];
#pragma unroll
        for (int j = 0; j < 8; ++j)
#pragma unroll
            for (int c = 0; c < 4; ++c) S[j][c] = 0.f;

#pragma unroll
        for (int kg = 0; kg < 4; ++kg) {
#pragma unroll
            for (int jj = 0; jj < 4; ++jj) {
                const uint32_t ka = sb + (uint32_t)(jj * 2304 + kg * 32) + rK;
                uint32_t kh0, kh1, kh2, kh3, kl0, kl1, kl2, kl3;
                LDSM_X4(kh0, kh1, kh2, kh3, ka);
                LDSM_X4(kl0, kl1, kl2, kl3, ka + MAT9);
                MMA16816(S[2 * jj],     qhf[kg], kh0, kh1);
                MMA16816(S[2 * jj + 1], qhf[kg], kh2, kh3);
                MMA16816(S[2 * jj],     qlf[kg], kh0, kh1);
                MMA16816(S[2 * jj + 1], qlf[kg], kh2, kh3);
                MMA16816(S[2 * jj],     qhf[kg], kl0, kl1);
                MMA16816(S[2 * jj + 1], qhf[kg], kl2, kl3);
            }
        }

        // ---- softmax + PV, interleaved per key-group ----
        if (kt < bulk) {
            FLASH_KG_BODY(false)
        } else {
            FLASH_KG_BODY(true)
        }
    }

    lg  += __shfl_xor_sync(0xffffffffu, lg, 1);
    lg  += __shfl_xor_sync(0xffffffffu, lg, 2);
    lg8 += __shfl_xor_sync(0xffffffffu, lg8, 1);
    lg8 += __shfl_xor_sync(0xffffffffu, lg8, 2);
    const float li0 = 1.0f / lg;
    const float li8 = 1.0f / lg8;

    const int b = bh >> 4, h = bh & 15;
    const int rq0g = qt * QTQ + w * 16 + g;
    const size_t ob0 = ((size_t)(b * T_SEQ + rq0g)) * D_MODEL + h * HD;
    const size_t ob1 = ((size_t)(b * T_SEQ + rq0g + 8)) * D_MODEL + h * HD;
#pragma unroll
    for (int j = 0; j < 8; ++j) {
        const int col = 8 * j + 2 * t;
        __nv_bfloat162 h2, l2;
        split2(O[j][0] * li0, O[j][1] * li0, h2, l2);
        *(__nv_bfloat162*)&g_Ah[ob0 + col] = h2;
        *(__nv_bfloat162*)&g_Al[ob0 + col] = l2;
        split2(O[j][2] * li8, O[j][3] * li8, h2, l2);
        *(__nv_bfloat162*)&g_Ah[ob1 + col] = h2;
        *(__nv_bfloat162*)&g_Al[ob1 + col] = l2;
    }
}

// ---------------------------------------------------------------------------
extern "C" void kernel_launch(void* const* d_in, const int* in_sizes, int n_in,
                              void* d_out, int out_size)
{
    (void)in_sizes; (void)n_in; (void)out_size;
    const float* x  = (const float*)d_in[0];
    const float* Wq = (const float*)d_in[1];
    const float* bq = (const float*)d_in[2];
    const float* Wk = (const float*)d_in[3];
    const float* bk = (const float*)d_in[4];
    const float* Wv = (const float*)d_in[5];
    const float* bv = (const float*)d_in[6];
    const float* Wo = (const float*)d_in[7];
    const float* bo = (const float*)d_in[8];
    float* out = (float*)d_out;

    cudaFuncSetAttribute(mma_gemm_kernel<true>,
                         cudaFuncAttributeMaxDynamicSharedMemorySize, GEMM_SMEM);
    cudaFuncSetAttribute(mma_gemm_kernel<false>,
                         cudaFuncAttributeMaxDynamicSharedMemorySize, GEMM_SMEM);
    cudaFuncSetAttribute(flash_fa2_kernel,
                         cudaFuncAttributeMaxDynamicSharedMemorySize, FL_SMEM);

    // 0) split x -> g_Ah/g_Al; transpose+split weights
    split_kernel<<<M_ROWS * D_MODEL / 1024, 256>>>(x);
    W4 w4; w4.W[0] = Wq; w4.W[1] = Wk; w4.W[2] = Wv; w4.W[3] = Wo;
    wtrans_kernel<<<dim3(32, 32, 4), 256>>>(w4);

    // 1) QKV projections (raw-mma GEMM; Q pre-scaled by QSCALE) -> bf16 hi/lo
    B3 bqkv; bqkv.b[0] = bq; bqkv.b[1] = bk; bqkv.b[2] = bv;
    mma_gemm_kernel<true><<<dim3(D_MODEL / 128, M_ROWS / 128, 3), 256, GEMM_SMEM>>>(bqkv, nullptr);

    // 2) causal flash v5.4 (ex2-only softmax, interleaved scalar) -> g_Ah/g_Al
    flash_fa2_kernel<<<dim3(T_SEQ / QTQ, BATCH * NH), FL_THR, FL_SMEM>>>();

    // 3) O projection (raw-mma GEMM) -> d_out
    B3 bout; bout.b[0] = bo; bout.b[1] = bo; bout.b[2] = bo;
    mma_gemm_kernel<false><<<dim3(D_MODEL / 128, M_ROWS / 128, 1), 256, GEMM_SMEM>>>(bout, out);
}

// round 17
// speedup vs baseline: 1.6694x; 1.4816x over previous
#include <cuda_runtime.h>
#include <cuda_fp16.h>
#include <cstdint>

// Problem constants
#define BATCH   4
#define T_SEQ   2048
#define D_MODEL 1024
#define NH      16
#define HD      64
#define M_ROWS  (BATCH * T_SEQ)   // 8192

// exp(q·k/8) == 2^((q*QSCALE)·k); Q pre-scaled in the QKV epilogue
#define QSCALE  0.18033688011112042f   // log2(e)/8

// ---------------------------------------------------------------------------
// Scratch (device globals; referenced ONLY inside device code — see R5 note)
// fp16 asymmetric split: A-operands (x / Q / P / o) split hi+lo, B-operands
// (W / K / V) plain fp16. 2 MMA products per k16 instead of 3.
// ---------------------------------------------------------------------------
__device__ __half g_qh[(size_t)BATCH * NH * T_SEQ * HD];  // Q hi (pre-scaled)
__device__ __half g_ql[(size_t)BATCH * NH * T_SEQ * HD];  // Q lo
__device__ __half g_kh[(size_t)BATCH * NH * T_SEQ * HD];  // K plain
__device__ __half g_vh[(size_t)BATCH * NH * T_SEQ * HD];  // V plain

__device__ __half g_Ah[(size_t)M_ROWS * D_MODEL];         // GEMM activation hi
__device__ __half g_Al[(size_t)M_ROWS * D_MODEL];         // GEMM activation lo
__device__ __half g_Wt[4][(size_t)D_MODEL * D_MODEL];     // W^T plain (K-major)

// ---------------------------------------------------------------------------
// sm_80-class PTX helpers (compute_103-safe)
// ---------------------------------------------------------------------------
__device__ __forceinline__ uint32_t smem_u32(const void* p) {
    uint32_t a;
    asm("{ .reg .u64 t; cvta.to.shared.u64 t, %1; cvt.u32.u64 %0, t; }" : "=r"(a) : "l"(p));
    return a;
}
#define CP_ASYNC16(saddr, gptr) \
    asm volatile("cp.async.cg.shared.global [%0], [%1], 16;" \
        :: "r"(saddr), "l"(gptr) : "memory")
#define CP_COMMIT() asm volatile("cp.async.commit_group;" ::: "memory")
#define CP_WAIT(n)  asm volatile("cp.async.wait_group %0;" :: "n"(n) : "memory")

#define LDSM_X4(r0, r1, r2, r3, addr) \
    asm volatile("ldmatrix.sync.aligned.m8n8.x4.shared.b16 {%0,%1,%2,%3}, [%4];" \
        : "=r"(r0), "=r"(r1), "=r"(r2), "=r"(r3) : "r"(addr))
#define LDSM_X4T(r0, r1, r2, r3, addr) \
    asm volatile("ldmatrix.sync.aligned.m8n8.x4.trans.shared.b16 {%0,%1,%2,%3}, [%4];" \
        : "=r"(r0), "=r"(r1), "=r"(r2), "=r"(r3) : "r"(addr))

// D += A*B, m16n8k16 row.col f32.f16.f16.f32
#define MMA16816(d, a, b0, b1) \
    asm volatile("mma.sync.aligned.m16n8k16.row.col.f32.f16.f16.f32 " \
        "{%0,%1,%2,%3}, {%4,%5,%6,%7}, {%8,%9}, {%0,%1,%2,%3};" \
        : "+f"((d)[0]), "+f"((d)[1]), "+f"((d)[2]), "+f"((d)[3]) \
        : "r"((a)[0]), "r"((a)[1]), "r"((a)[2]), "r"((a)[3]), "r"(b0), "r"(b1))

struct B3 { const float* b[3]; };
struct W4 { const float* W[4]; };

__device__ __forceinline__ float ex2a(float x) {
    float r;
    asm("ex2.approx.f32 %0, %1;" : "=f"(r) : "f"(x));
    return r;
}

__device__ __forceinline__ void split2h(float a, float b, __half2& h, __half2& l) {
    __half ha = __float2half(a), hb = __float2half(b);
    h.x = ha; h.y = hb;
    l.x = __float2half(a - __half2float(ha));
    l.y = __float2half(b - __half2float(hb));
}
// packed: h/l as uint32 f16x2 via cvt.rn.f16x2.f32 (low=a, high=b)
__device__ __forceinline__ void split2p(float a, float b, uint32_t& h, uint32_t& l) {
    asm("cvt.rn.f16x2.f32 %0, %1, %2;" : "=r"(h) : "f"(b), "f"(a));
    const __half2 hv = *(const __half2*)&h;
    const float ra = a - __half2float(hv.x);
    const float rb = b - __half2float(hv.y);
    asm("cvt.rn.f16x2.f32 %0, %1, %2;" : "=r"(l) : "f"(rb), "f"(ra));
}

// ---------------------------------------------------------------------------
// fp32 x -> fp16 hi/lo split (elementwise) into g_Ah/g_Al
// ---------------------------------------------------------------------------
__global__ __launch_bounds__(256)
void split_kernel(const float* __restrict__ xsrc)
{
    const int i = blockIdx.x * 256 + threadIdx.x;   // float4 index
    float4 v = ((const float4*)xsrc)[i];
    __half2 h0, l0, h1, l1;
    split2h(v.x, v.y, h0, l0);
    split2h(v.z, v.w, h1, l1);
    ((__half2*)g_Ah)[i * 2 + 0] = h0;
    ((__half2*)g_Ah)[i * 2 + 1] = h1;
    ((__half2*)g_Al)[i * 2 + 0] = l0;
    ((__half2*)g_Al)[i * 2 + 1] = l1;
}

// ---------------------------------------------------------------------------
// W [k,n] fp32 -> W^T [n,k] plain fp16, all 4 weights (z)
// ---------------------------------------------------------------------------
__global__ __launch_bounds__(256)
void wtrans_kernel(W4 w)
{
    __shared__ float tile[32][33];
    const int z = blockIdx.z;
    const float* __restrict__ W = w.W[z];
    const int n0 = blockIdx.x * 32, k0 = blockIdx.y * 32;
    const int tx = threadIdx.x & 31, ty = threadIdx.x >> 5;  // 32 x 8
#pragma unroll
    for (int i = 0; i < 4; i++)
        tile[ty + i * 8][tx] = W[(size_t)(k0 + ty + i * 8) * D_MODEL + n0 + tx];
    __syncthreads();
#pragma unroll
    for (int i = 0; i < 4; i++) {
        float v = tile[tx][ty + i * 8];
        g_Wt[z][(size_t)(n0 + ty + i * 8) * D_MODEL + k0 + tx] = __float2half(v);
    }
}

// ---------------------------------------------------------------------------
// RAW-MMA GEMM (R17): fp16 asymmetric 2-product, warp tile 32x64.
// 8 warps = 4(M, 32 rows) x 2(N, 64 cols): A re-read 2x, B re-read 4x
// (80KB fragment traffic/chunk, was 120KB). Fragment recipes R10-proven.
// Direct-register epilogue: z==0 -> Q hi/lo (pre-scaled); z==1/2 -> K/V plain;
// z==3 -> fp32 Cout + bias.
// ---------------------------------------------------------------------------
#define BK        32
#define GFLD      80                           // bytes per 32-fp16 row (padded)
#define GMAT      (128 * GFLD)                 // 10240
#define GSTG      (3 * GMAT)                   // 30720: Ah Al B
#define GEMM_SMEM (2 * GSTG)                   // 61440 -> 2 blocks/SM
#define NCHUNKS   (D_MODEL / BK)               // 32

template <bool QKV>
__global__ __launch_bounds__(256, 2)
void mma_gemm_kernel(B3 biases, float* __restrict__ Cout)
{
    extern __shared__ char smc[];
    const uint32_t smb = smem_u32(smc);
    const int tid  = threadIdx.x;
    const int wid  = tid >> 5;
    const int lane = tid & 31;
    const int g    = lane >> 2;
    const int t    = lane & 3;

    const int z = QKV ? blockIdx.z : 3;
    const int rowBase = blockIdx.y * 128;
    const int colBase = blockIdx.x * 128;
    const float* __restrict__ bias = QKV ? biases.b[z] : biases.b[0];

    const __half* __restrict__ src[3] = {
        g_Ah + (size_t)rowBase * D_MODEL,
        g_Al + (size_t)rowBase * D_MODEL,
        g_Wt[z] + (size_t)colBase * D_MODEL
    };

    const int wm = wid & 3;          // M quarter (32 rows)
    const int wn = wid >> 2;         // N half (64 cols)

    const uint32_t rA = (uint32_t)((lane & 15) * GFLD + ((lane & 16) ? 16 : 0));
    const uint32_t rB = (uint32_t)(((lane & 7) + ((lane & 16) ? 8 : 0)) * GFLD
                                   + ((lane & 8) ? 16 : 0));

    float acc[2][8][4];              // [mf][n8][4]
#pragma unroll
    for (int mf = 0; mf < 2; ++mf)
#pragma unroll
        for (int n8 = 0; n8 < 8; ++n8)
#pragma unroll
            for (int c = 0; c < 4; ++c) acc[mf][n8][c] = 0.f;

    auto load_stage = [&](int stage, int k0) {
        const uint32_t sb = smb + stage * GSTG;
#pragma unroll
        for (int mat = 0; mat < 3; ++mat) {
#pragma unroll
            for (int half = 0; half < 2; ++half) {
                const int e = tid + half * 256;      // 0..511
                const int row = e >> 2;              // 0..127
                const int c4 = e & 3;                // 16B chunk
                CP_ASYNC16(sb + (uint32_t)(mat * GMAT + row * GFLD + c4 * 16),
                           src[mat] + (size_t)row * D_MODEL + k0 + c4 * 8);
            }
        }
        CP_COMMIT();
    };

    load_stage(0, 0);

    for (int c = 0; c < NCHUNKS; ++c) {
        CP_WAIT(0);            // stage c landed
        __syncthreads();       // all warps past compute(c-1)
        if (c + 1 < NCHUNKS) load_stage((c + 1) & 1, (c + 1) * BK);

        const uint32_t sb = smb + (c & 1) * GSTG;
        const uint32_t aRow = sb + (uint32_t)(wm * 32) * GFLD + rA;
        const uint32_t bRow = sb + 2 * GMAT + (uint32_t)(wn * 64) * GFLD + rB;

#pragma unroll
        for (int ks = 0; ks < 2; ++ks) {
            const uint32_t ko = (uint32_t)(ks * 32);
            uint32_t ah[2][4], al[2][4], bb[4][4];
#pragma unroll
            for (int mf = 0; mf < 2; ++mf) {
                LDSM_X4(ah[mf][0], ah[mf][1], ah[mf][2], ah[mf][3],
                        aRow + (uint32_t)(mf * 16) * GFLD + ko);
                LDSM_X4(al[mf][0], al[mf][1], al[mf][2], al[mf][3],
                        aRow + GMAT + (uint32_t)(mf * 16) * GFLD + ko);
            }
#pragma unroll
            for (int j2 = 0; j2 < 4; ++j2)
                LDSM_X4(bb[j2][0], bb[j2][1], bb[j2][2], bb[j2][3],
                        bRow + (uint32_t)(j2 * 16) * GFLD + ko);
            // term 1: Ah x B
#pragma unroll
            for (int mf = 0; mf < 2; ++mf)
#pragma unroll
                for (int j2 = 0; j2 < 4; ++j2) {
                    MMA16816(acc[mf][2 * j2],     ah[mf], bb[j2][0], bb[j2][1]);
                    MMA16816(acc[mf][2 * j2 + 1], ah[mf], bb[j2][2], bb[j2][3]);
                }
            // term 2: Al x B
#pragma unroll
            for (int mf = 0; mf < 2; ++mf)
#pragma unroll
                for (int j2 = 0; j2 < 4; ++j2) {
                    MMA16816(acc[mf][2 * j2],     al[mf], bb[j2][0], bb[j2][1]);
                    MMA16816(acc[mf][2 * j2 + 1], al[mf], bb[j2][2], bb[j2][3]);
                }
        }
    }

    // ---- direct-register epilogue ----
    const float osc = (QKV && z == 0) ? QSCALE : 1.0f;   // fold softmax scale into Q
#pragma unroll
    for (int mf = 0; mf < 2; ++mf) {
        const int row0 = rowBase + wm * 32 + mf * 16 + g;
#pragma unroll
        for (int n8 = 0; n8 < 8; ++n8) {
            const int col = colBase + wn * 64 + n8 * 8 + 2 * t;
            const float bx = __ldg(&bias[col]);
            const float by = __ldg(&bias[col + 1]);
            float2 v0 = { (acc[mf][n8][0] + bx) * osc, (acc[mf][n8][1] + by) * osc };
            float2 v1 = { (acc[mf][n8][2] + bx) * osc, (acc[mf][n8][3] + by) * osc };
            if (QKV) {
                const int hd = col & 63;
                const int hh = col >> 6;
#pragma unroll
                for (int r = 0; r < 2; ++r) {
                    const int row = row0 + r * 8;
                    const int bh_ = (row >> 11) * NH + hh;
                    const int tt  = row & 2047;
                    const size_t o = ((size_t)bh_ * T_SEQ + tt) * HD + hd;
                    const float vx = r ? v1.x : v0.x;
                    const float vy = r ? v1.y : v0.y;
                    if (z == 0) {                    // Q: split hi/lo
                        __half2 h2, l2;
                        split2h(vx, vy, h2, l2);
                        *(__half2*)(g_qh + o) = h2;
                        *(__half2*)(g_ql + o) = l2;
                    } else {                         // K/V: plain fp16
                        __half2 p2;
                        p2.x = __float2half(vx);
                        p2.y = __float2half(vy);
                        *(__half2*)((z == 1 ? g_kh : g_vh) + o) = p2;
                    }
                }
            } else {
                *(float2*)&Cout[(size_t)row0 * D_MODEL + col] = v0;
                *(float2*)&Cout[(size_t)(row0 + 8) * D_MODEL + col] = v1;
            }
        }
    }
}

// ---------------------------------------------------------------------------
// Flash v6: fp16 asymmetric 2-product (Q/P split hi/lo, K/V plain).
// Per iter: 32 LDSM (was 64), 128 MMA (was 192). Structure otherwise = R16
// (proven): ex2-only softmax, diagonal-only masking, interleaved scalar.
// ---------------------------------------------------------------------------
#define QTQ      128
#define KTK      64
#define FL_THR   256
#define FLD      144
#define MAT9     (KTK * FLD)                   // 9216
#define STG_B    (2 * MAT9)                    // 18432: K V
#define Q_OFF    (3 * STG_B)                   // 55296
#define QMATB    (QTQ * FLD)                   // 18432
#define FL_SMEM  (Q_OFF + 2 * QMATB)           // 92160 -> 2 blocks/SM

#define FLASH_KG_BODY(MASKED)                                                 \
_Pragma("unroll")                                                             \
    for (int kg = 0; kg < 4; ++kg) {                                          \
_Pragma("unroll")                                                             \
        for (int jj2 = 0; jj2 < 2; ++jj2) {                                   \
            const int j = 2 * kg + jj2;                                       \
            if (MASKED) {                                                     \
                const int kb = kt * KTK + 8 * j + 2 * t;                      \
                S[j][0] = (kb     <= rq0) ? ex2a(S[j][0]) : 0.f;              \
                S[j][1] = (kb + 1 <= rq0) ? ex2a(S[j][1]) : 0.f;              \
                S[j][2] = (kb     <= rq1) ? ex2a(S[j][2]) : 0.f;              \
                S[j][3] = (kb + 1 <= rq1) ? ex2a(S[j][3]) : 0.f;              \
            } else {                                                          \
                S[j][0] = ex2a(S[j][0]);                                      \
                S[j][1] = ex2a(S[j][1]);                                      \
                S[j][2] = ex2a(S[j][2]);                                      \
                S[j][3] = ex2a(S[j][3]);                                      \
            }                                                                 \
            lg  += S[j][0] + S[j][1];                                         \
            lg8 += S[j][2] + S[j][3];                                         \
        }                                                                     \
        uint32_t ph[4], pl[4];                                                \
        split2p(S[2 * kg][0],     S[2 * kg][1],     ph[0], pl[0]);            \
        split2p(S[2 * kg][2],     S[2 * kg][3],     ph[1], pl[1]);            \
        split2p(S[2 * kg + 1][0], S[2 * kg + 1][1], ph[2], pl[2]);            \
        split2p(S[2 * kg + 1][2], S[2 * kg + 1][3], ph[3], pl[3]);            \
_Pragma("unroll")                                                             \
        for (int jj = 0; jj < 4; ++jj) {                                      \
            const uint32_t va = sb + (uint32_t)(MAT9 + kg * 2304 + jj * 32) + rV; \
            uint32_t vh0, vh1, vh2, vh3;                                      \
            LDSM_X4T(vh0, vh1, vh2, vh3, va);                                 \
            MMA16816(O[2 * jj],     ph, vh0, vh1);                            \
            MMA16816(O[2 * jj + 1], ph, vh2, vh3);                            \
            MMA16816(O[2 * jj],     pl, vh0, vh1);                            \
            MMA16816(O[2 * jj + 1], pl, vh2, vh3);                            \
        }                                                                     \
    }

__global__ __launch_bounds__(FL_THR, 2)
void flash_fa2_kernel()
{
    extern __shared__ char smf[];
    const uint32_t smb = smem_u32(smf);

    const int tid  = threadIdx.x;
    const int w    = tid >> 5;
    const int lane = tid & 31;
    const int g    = lane >> 2;
    const int t    = lane & 3;
    const int bh   = blockIdx.y;
    const int qt   = gridDim.x - 1 - blockIdx.x;
    const int ktmax = 2 * qt + 1;
    const int bulk  = 2 * qt;                  // tiles < bulk need no mask

    const size_t base = (size_t)bh * T_SEQ * HD;

    const uint32_t rK = (uint32_t)(((lane & 7) + ((lane & 16) ? 8 : 0)) * FLD
                                   + ((lane & 8) ? 16 : 0));
    const uint32_t rV = (uint32_t)(((lane & 7) + ((lane & 8) ? 8 : 0)) * FLD
                                   + ((lane & 16) ? 16 : 0));
    const uint32_t rQ = (uint32_t)((lane & 15) * FLD + ((lane & 16) ? 16 : 0));

    // ---- stage Q (hi/lo) into dedicated region; prefetch kt=0 ----
    {
        const __half* qsrc[2] = { g_qh + base + (size_t)qt * QTQ * HD,
                                  g_ql + base + (size_t)qt * QTQ * HD };
#pragma unroll
        for (int m = 0; m < 2; ++m) {
            const uint32_t dst = smb + Q_OFF + m * QMATB;
#pragma unroll
            for (int it = 0; it < 4; ++it) {
                const int e = tid + it * FL_THR;
                const int r = e >> 3, s = e & 7;
                CP_ASYNC16(dst + (uint32_t)(r * FLD + s * 16),
                           qsrc[m] + (size_t)r * HD + s * 8);
            }
        }
        CP_COMMIT();
    }
    auto prefetch = [&](int kt_, int stage) {
        const uint32_t sb = smb + stage * STG_B;
        const size_t kb = base + (size_t)kt_ * KTK * HD;
        const __half* gsrc[2] = { g_kh + kb, g_vh + kb };
#pragma unroll
        for (int mat = 0; mat < 2; ++mat) {
#pragma unroll
            for (int it = 0; it < 2; ++it) {
                const int e = tid + it * FL_THR;
                const int r = e >> 3, s = e & 7;
                CP_ASYNC16(sb + (uint32_t)(mat * MAT9 + r * FLD + s * 16),
                           gsrc[mat] + (size_t)r * HD + s * 8);
            }
        }
        CP_COMMIT();
    };
    prefetch(0, 0);
    CP_WAIT(1);     // Q staged
    __syncthreads();

    uint32_t qhf[4][4], qlf[4][4];
    {
        const uint32_t q2 = smb + Q_OFF + (uint32_t)(w * 16) * FLD + rQ;
#pragma unroll
        for (int kg = 0; kg < 4; ++kg) {
            LDSM_X4(qhf[kg][0], qhf[kg][1], qhf[kg][2], qhf[kg][3], q2 + kg * 32);
            LDSM_X4(qlf[kg][0], qlf[kg][1], qlf[kg][2], qlf[kg][3],
                    q2 + (uint32_t)QMATB + kg * 32);
        }
    }
    if (1 <= ktmax) prefetch(1, 1); else CP_COMMIT();

    float O[8][4];
#pragma unroll
    for (int j = 0; j < 8; ++j)
#pragma unroll
        for (int c = 0; c < 4; ++c) O[j][c] = 0.f;
    float lg = 0.f, lg8 = 0.f;
    const int rq0 = qt * QTQ + w * 16 + g;
    const int rq1 = rq0 + 8;

    for (int kt = 0; kt <= ktmax; ++kt) {
        CP_WAIT(1);
        __syncthreads();
        if (kt + 2 <= ktmax) prefetch(kt + 2, (kt + 2) % 3); else CP_COMMIT();

        const uint32_t sb = smb + (kt % 3) * STG_B;

        // ---- S = Q K^T (2-product) ----
        float S[8][4];
#pragma unroll
        for (int j = 0; j < 8; ++j)
#pragma unroll
            for (int c = 0; c < 4; ++c) S[j][c] = 0.f;

#pragma unroll
        for (int kg = 0; kg < 4; ++kg) {
#pragma unroll
            for (int jj = 0; jj < 4; ++jj) {
                const uint32_t ka = sb + (uint32_t)(jj * 2304 + kg * 32) + rK;
                uint32_t kh0, kh1, kh2, kh3;
                LDSM_X4(kh0, kh1, kh2, kh3, ka);
                MMA16816(S[2 * jj],     qhf[kg], kh0, kh1);
                MMA16816(S[2 * jj + 1], qhf[kg], kh2, kh3);
                MMA16816(S[2 * jj],     qlf[kg], kh0, kh1);
                MMA16816(S[2 * jj + 1], qlf[kg], kh2, kh3);
            }
        }

        // ---- softmax + PV (2-product), interleaved per key-group ----
        if (kt < bulk) {
            FLASH_KG_BODY(false)
        } else {
            FLASH_KG_BODY(true)
        }
    }

    lg  += __shfl_xor_sync(0xffffffffu, lg, 1);
    lg  += __shfl_xor_sync(0xffffffffu, lg, 2);
    lg8 += __shfl_xor_sync(0xffffffffu, lg8, 1);
    lg8 += __shfl_xor_sync(0xffffffffu, lg8, 2);
    const float li0 = 1.0f / lg;
    const float li8 = 1.0f / lg8;

    const int b = bh >> 4, h = bh & 15;
    const int rq0g = qt * QTQ + w * 16 + g;
    const size_t ob0 = ((size_t)(b * T_SEQ + rq0g)) * D_MODEL + h * HD;
    const size_t ob1 = ((size_t)(b * T_SEQ + rq0g + 8)) * D_MODEL + h * HD;
#pragma unroll
    for (int j = 0; j < 8; ++j) {
        const int col = 8 * j + 2 * t;
        uint32_t h2, l2;
        split2p(O[j][0] * li0, O[j][1] * li0, h2, l2);
        *(uint32_t*)(g_Ah + ob0 + col) = h2;
        *(uint32_t*)(g_Al + ob0 + col) = l2;
        split2p(O[j][2] * li8, O[j][3] * li8, h2, l2);
        *(uint32_t*)(g_Ah + ob1 + col) = h2;
        *(uint32_t*)(g_Al + ob1 + col) = l2;
    }
}

// ---------------------------------------------------------------------------
extern "C" void kernel_launch(void* const* d_in, const int* in_sizes, int n_in,
                              void* d_out, int out_size)
{
    (void)in_sizes; (void)n_in; (void)out_size;
    const float* x  = (const float*)d_in[0];
    const float* Wq = (const float*)d_in[1];
    const float* bq = (const float*)d_in[2];
    const float* Wk = (const float*)d_in[3];
    const float* bk = (const float*)d_in[4];
    const float* Wv = (const float*)d_in[5];
    const float* bv = (const float*)d_in[6];
    const float* Wo = (const float*)d_in[7];
    const float* bo = (const float*)d_in[8];
    float* out = (float*)d_out;

    cudaFuncSetAttribute(mma_gemm_kernel<true>,
                         cudaFuncAttributeMaxDynamicSharedMemorySize, GEMM_SMEM);
    cudaFuncSetAttribute(mma_gemm_kernel<false>,
                         cudaFuncAttributeMaxDynamicSharedMemorySize, GEMM_SMEM);
    cudaFuncSetAttribute(flash_fa2_kernel,
                         cudaFuncAttributeMaxDynamicSharedMemorySize, FL_SMEM);

    // 0) split x -> g_Ah/g_Al (fp16 hi/lo); transpose weights (plain fp16)
    split_kernel<<<M_ROWS * D_MODEL / 1024, 256>>>(x);
    W4 w4; w4.W[0] = Wq; w4.W[1] = Wk; w4.W[2] = Wv; w4.W[3] = Wo;
    wtrans_kernel<<<dim3(32, 32, 4), 256>>>(w4);

    // 1) QKV projections (fp16 2-product; Q pre-scaled + split, K/V plain)
    B3 bqkv; bqkv.b[0] = bq; bqkv.b[1] = bk; bqkv.b[2] = bv;
    mma_gemm_kernel<true><<<dim3(D_MODEL / 128, M_ROWS / 128, 3), 256, GEMM_SMEM>>>(bqkv, nullptr);

    // 2) causal flash v6 (fp16 2-product) -> g_Ah/g_Al
    flash_fa2_kernel<<<dim3(T_SEQ / QTQ, BATCH * NH), FL_THR, FL_SMEM>>>();

    // 3) O projection (fp16 2-product) -> d_out
    B3 bout; bout.b[0] = bo; bout.b[1] = bo; bout.b[2] = bo;
    mma_gemm_kernel<false><<<dim3(D_MODEL / 128, M_ROWS / 128, 1), 256, GEMM_SMEM>>>(bout, out);
}